// round 12
// baseline (speedup 1.0000x reference)
#include <cuda_runtime.h>
#include <cuda_fp16.h>
#include <math.h>
#include <stdint.h>

// Problem constants
#define B_   8
#define C_   512
#define N_   3136   // 56*56
#define NP_  3200   // N padded to multiple of 128
#define IC_  256
#define ROWS_TOTAL (B_ * N_)   // 25088

// ---------------------------------------------------------------------------
// Scratch
// ---------------------------------------------------------------------------
__device__ __half g_xh [(size_t)B_ * NP_ * C_];   // x fp16 transposed [token][c]
__device__ __half g_Wh [(size_t)3 * IC_ * C_];    // theta/phi/g weights fp16
__device__ __half g_wzh[(size_t)C_ * IC_];        // wz fp16
__device__ __half g_Qh [(size_t)B_ * NP_ * IC_];  // Q fp16 [token][i]
__device__ __half g_Kh [(size_t)B_ * NP_ * IC_];  // K fp16 [token][i]
__device__ __half g_Vt [(size_t)B_ * IC_ * NP_];  // V fp16 transposed [i][token]
__device__ float  g_S  [(size_t)B_ * NP_ * NP_];  // logits fp32
__device__ __half g_P  [(size_t)B_ * NP_ * NP_];  // softmax probs fp16
__device__ __half g_y1h[(size_t)B_ * NP_ * IC_];  // attention out fp16
__device__ float  g_y2 [(size_t)B_ * N_ * C_];
__device__ double g_sum[C_];
__device__ double g_sumsq[C_];

// ---------------------------------------------------------------------------
// mma / ldmatrix helpers
// ---------------------------------------------------------------------------
__device__ __forceinline__ void mma_f16(float& d0, float& d1, float& d2, float& d3,
                                        uint32_t a0, uint32_t a1, uint32_t a2, uint32_t a3,
                                        uint32_t b0, uint32_t b1) {
    asm volatile(
        "mma.sync.aligned.m16n8k16.row.col.f32.f16.f16.f32 "
        "{%0,%1,%2,%3}, {%4,%5,%6,%7}, {%8,%9}, {%0,%1,%2,%3};\n"
        : "+f"(d0), "+f"(d1), "+f"(d2), "+f"(d3)
        : "r"(a0), "r"(a1), "r"(a2), "r"(a3), "r"(b0), "r"(b1));
}
__device__ __forceinline__ void ldsm_x4(uint32_t& r0, uint32_t& r1, uint32_t& r2, uint32_t& r3,
                                        uint32_t addr) {
    asm volatile("ldmatrix.sync.aligned.m8n8.x4.shared.b16 {%0,%1,%2,%3}, [%4];"
                 : "=r"(r0), "=r"(r1), "=r"(r2), "=r"(r3) : "r"(addr));
}
__device__ __forceinline__ uint32_t smem_u32(const void* p) {
    return (uint32_t)__cvta_generic_to_shared(p);
}

constexpr int FSTR = 20;       // 20 words = 80 bytes per SMEM row (32 data halves + pad)
constexpr int FSTRB = 80;      // bytes

// ---------------------------------------------------------------------------
// Prep kernels
// ---------------------------------------------------------------------------
__global__ void conv_weights(const float* __restrict__ tw, const float* __restrict__ pw,
                             const float* __restrict__ gw, const float* __restrict__ wz)
{
    const int WSZ = IC_ * C_;            // 131072
    int idx = blockIdx.x * 256 + threadIdx.x;
    if (idx < 3 * WSZ) {
        const float* src = (idx < WSZ) ? tw : (idx < 2 * WSZ ? pw : gw);
        g_Wh[idx] = __float2half_rn(src[idx % WSZ]);
    } else {
        int off = idx - 3 * WSZ;
        g_wzh[off] = __float2half_rn(wz[off]);
    }
}

__global__ __launch_bounds__(256) void x_to_h(const float* __restrict__ x)
{
    __shared__ float t[32][33];
    const int b  = blockIdx.z;
    const int n0 = blockIdx.x * 32;
    const int c0 = blockIdx.y * 32;
    const float* xb = x + (size_t)b * C_ * N_;
    __half* xh = g_xh + (size_t)b * NP_ * C_;
    const int tx = threadIdx.x, ty = threadIdx.y;

    #pragma unroll
    for (int j = 0; j < 32; j += 8)
        t[ty + j][tx] = xb[(size_t)(c0 + ty + j) * N_ + n0 + tx];
    __syncthreads();
    #pragma unroll
    for (int j = 0; j < 32; j += 8)
        xh[(size_t)(n0 + ty + j) * C_ + c0 + tx] = __float2half_rn(t[tx][ty + j]);
}

// ===========================================================================
// Fused QKV: fp16 mma + ldmatrix. Block 64(m) x 192(3x64 n), 4 warps,
// warp tile 64m x 48n over the concatenated [theta|phi|g] B tile.
// Double-buffered k=32 slices over C_=512.
// ===========================================================================
__global__ __launch_bounds__(128) void qkv3_f16(
    const float* __restrict__ tb, const float* __restrict__ pb,
    const float* __restrict__ gb,
    __half* __restrict__ Q, __half* __restrict__ K, __half* __restrict__ Vt)
{
    const long long z = blockIdx.z;
    const __half* xh = g_xh + z * (long long)NP_ * C_;
    Q  += z * (long long)NP_ * IC_;
    K  += z * (long long)NP_ * IC_;
    Vt += z * (long long)IC_ * NP_;

    const int m0 = blockIdx.x * 64;
    const int n0 = blockIdx.y * 64;   // 64-col window into IC for all 3 outputs
    const int tid = threadIdx.x;
    const int w = tid >> 5, lane = tid & 31;
    const int gid = lane >> 2, tig = lane & 3;

    __shared__ uint32_t Ah[2][64 * FSTR];
    __shared__ uint32_t Bh[2][192 * FSTR];

    const int a_row = (lane & 7) + ((lane >> 3) & 1) * 8;
    const int a_kb  = (lane >> 4) * 16;
    const int b_row = (lane & 7) + (lane >> 4) * 8;
    const int b_kb  = ((lane >> 3) & 1) * 16;

    float acc[4][6][4];   // [m-tile][n-tile][reg]
    #pragma unroll
    for (int i = 0; i < 4; i++)
        #pragma unroll
        for (int j = 0; j < 6; j++)
            #pragma unroll
            for (int r = 0; r < 4; r++) acc[i][j][r] = 0.0f;

    uint4 ra[2], rb[6];
    auto gload = [&](int k0) {
        #pragma unroll
        for (int it = 0; it < 2; it++) {
            int lin = tid + it * 128;
            int row = lin >> 2, k8 = (lin & 3) << 3;
            ra[it] = *(const uint4*)(xh + (long long)(m0 + row) * C_ + k0 + k8);
        }
        #pragma unroll
        for (int it = 0; it < 6; it++) {
            int lin = tid + it * 128;
            int brow = lin >> 2, k8 = (lin & 3) << 3;
            int s = brow >> 6, wr = brow & 63;
            rb[it] = *(const uint4*)(g_Wh + ((long long)s * IC_ + n0 + wr) * C_ + k0 + k8);
        }
    };
    auto sstore = [&](int b) {
        #pragma unroll
        for (int it = 0; it < 2; it++) {
            int lin = tid + it * 128;
            int row = lin >> 2, kw = (lin & 3) << 2;
            *(uint4*)(&Ah[b][row * FSTR + kw]) = ra[it];
        }
        #pragma unroll
        for (int it = 0; it < 6; it++) {
            int lin = tid + it * 128;
            int brow = lin >> 2, kw = (lin & 3) << 2;
            *(uint4*)(&Bh[b][brow * FSTR + kw]) = rb[it];
        }
    };

    gload(0); sstore(0); __syncthreads();
    int buf = 0;
    for (int k0 = 0; k0 < C_; k0 += 32) {
        const bool nxt = (k0 + 32 < C_);
        if (nxt) gload(k0 + 32);

        const uint32_t abase = smem_u32(Ah[buf]);
        const uint32_t bbase = smem_u32(Bh[buf]);
        #pragma unroll
        for (int ks = 0; ks < 2; ks++) {
            const int kb = ks * 32;
            uint32_t af[4][4];
            #pragma unroll
            for (int i = 0; i < 4; i++)
                ldsm_x4(af[i][0], af[i][1], af[i][2], af[i][3],
                        abase + (i * 16 + a_row) * FSTRB + kb + a_kb);
            uint32_t bf[6][2];
            #pragma unroll
            for (int jj = 0; jj < 3; jj++)
                ldsm_x4(bf[jj * 2][0], bf[jj * 2][1], bf[jj * 2 + 1][0], bf[jj * 2 + 1][1],
                        bbase + (w * 48 + jj * 16 + b_row) * FSTRB + kb + b_kb);
            #pragma unroll
            for (int i = 0; i < 4; i++)
                #pragma unroll
                for (int j = 0; j < 6; j++)
                    mma_f16(acc[i][j][0], acc[i][j][1], acc[i][j][2], acc[i][j][3],
                            af[i][0], af[i][1], af[i][2], af[i][3],
                            bf[j][0], bf[j][1]);
        }
        if (nxt) { sstore(buf ^ 1); __syncthreads(); buf ^= 1; }
    }

    // epilogue: demux the 192-col window into Q / K / Vt
    const float* biases[3] = {tb, pb, gb};
    #pragma unroll
    for (int j = 0; j < 6; j++) {
        int col192 = w * 48 + j * 8 + tig * 2;   // 8-col tiles never cross s-boundary
        int s = col192 >> 6;
        int gcol = n0 + (col192 & 63);
        float b0v = biases[s][gcol], b1v = biases[s][gcol + 1];
        #pragma unroll
        for (int i = 0; i < 4; i++) {
            int grow = m0 + i * 16 + gid;
            float v00 = acc[i][j][0] + b0v;
            float v01 = acc[i][j][1] + b1v;
            float v10 = acc[i][j][2] + b0v;
            float v11 = acc[i][j][3] + b1v;
            if (s == 0) {
                *(__half2*)(Q + (long long)grow * IC_ + gcol)       = __floats2half2_rn(v00, v01);
                *(__half2*)(Q + (long long)(grow + 8) * IC_ + gcol) = __floats2half2_rn(v10, v11);
            } else if (s == 1) {
                *(__half2*)(K + (long long)grow * IC_ + gcol)       = __floats2half2_rn(v00, v01);
                *(__half2*)(K + (long long)(grow + 8) * IC_ + gcol) = __floats2half2_rn(v10, v11);
            } else {
                Vt[(long long)gcol       * NP_ + grow]     = __float2half_rn(v00);
                Vt[(long long)(gcol + 1) * NP_ + grow]     = __float2half_rn(v01);
                Vt[(long long)gcol       * NP_ + grow + 8] = __float2half_rn(v10);
                Vt[(long long)(gcol + 1) * NP_ + grow + 8] = __float2half_rn(v11);
            }
        }
    }
}

// ===========================================================================
// Generic fp16 mma GEMM + ldmatrix, 128x128x32 double-buffered.
// 4 warps (2x2), warp tile 64x64 -> 8 LDSM.x4 per 32 MMAs.
// ===========================================================================
template<bool HALF_OUT>
__global__ __launch_bounds__(128) void gemm_f16(
    const __half* __restrict__ A, const __half* __restrict__ Bm,
    void* __restrict__ Cc,
    int K, int sA, int sB, int ldc,
    long long batA, long long batB, long long batC)
{
    const long long z = blockIdx.z;
    A  += z * batA;
    Bm += z * batB;

    const int m0 = blockIdx.x * 128;
    const int n0 = blockIdx.y * 128;
    const int tid = threadIdx.x;
    const int w = tid >> 5, lane = tid & 31;
    const int gid = lane >> 2, tig = lane & 3;
    const int wm = (w & 1) * 64, wn = (w >> 1) * 64;

    __shared__ uint32_t As[2][128 * FSTR];
    __shared__ uint32_t Bs[2][128 * FSTR];

    const int a_row = (lane & 7) + ((lane >> 3) & 1) * 8;
    const int a_kb  = (lane >> 4) * 16;
    const int b_row = (lane & 7) + (lane >> 4) * 8;
    const int b_kb  = ((lane >> 3) & 1) * 16;

    float acc[4][8][4];
    #pragma unroll
    for (int i = 0; i < 4; i++)
        #pragma unroll
        for (int j = 0; j < 8; j++)
            #pragma unroll
            for (int r = 0; r < 4; r++) acc[i][j][r] = 0.0f;

    uint4 ra[4], rb[4];
    auto gload = [&](int k0) {
        #pragma unroll
        for (int it = 0; it < 4; it++) {
            int lin = tid + it * 128;
            int row = lin >> 2, k8 = (lin & 3) << 3;
            ra[it] = *(const uint4*)(A  + (long long)(m0 + row) * sA + k0 + k8);
            rb[it] = *(const uint4*)(Bm + (long long)(n0 + row) * sB + k0 + k8);
        }
    };
    auto sstore = [&](int b) {
        #pragma unroll
        for (int it = 0; it < 4; it++) {
            int lin = tid + it * 128;
            int row = lin >> 2, kw = (lin & 3) << 2;
            *(uint4*)(&As[b][row * FSTR + kw]) = ra[it];
            *(uint4*)(&Bs[b][row * FSTR + kw]) = rb[it];
        }
    };

    gload(0); sstore(0); __syncthreads();
    int buf = 0;
    for (int k0 = 0; k0 < K; k0 += 32) {
        const bool nxt = (k0 + 32 < K);
        if (nxt) gload(k0 + 32);

        const uint32_t abase = smem_u32(As[buf]);
        const uint32_t bbase = smem_u32(Bs[buf]);
        #pragma unroll
        for (int ks = 0; ks < 2; ks++) {
            const int kb = ks * 32;
            uint32_t af[4][4];
            #pragma unroll
            for (int i = 0; i < 4; i++)
                ldsm_x4(af[i][0], af[i][1], af[i][2], af[i][3],
                        abase + (wm + i * 16 + a_row) * FSTRB + kb + a_kb);
            uint32_t bf[8][2];
            #pragma unroll
            for (int jj = 0; jj < 4; jj++)
                ldsm_x4(bf[jj * 2][0], bf[jj * 2][1], bf[jj * 2 + 1][0], bf[jj * 2 + 1][1],
                        bbase + (wn + jj * 16 + b_row) * FSTRB + kb + b_kb);
            #pragma unroll
            for (int i = 0; i < 4; i++)
                #pragma unroll
                for (int j = 0; j < 8; j++)
                    mma_f16(acc[i][j][0], acc[i][j][1], acc[i][j][2], acc[i][j][3],
                            af[i][0], af[i][1], af[i][2], af[i][3],
                            bf[j][0], bf[j][1]);
        }
        if (nxt) { sstore(buf ^ 1); __syncthreads(); buf ^= 1; }
    }

    #pragma unroll
    for (int i = 0; i < 4; i++) {
        int grow = m0 + wm + i * 16 + gid;
        #pragma unroll
        for (int j = 0; j < 8; j++) {
            int gcol = n0 + wn + j * 8 + tig * 2;
            if (HALF_OUT) {
                __half* C = (__half*)Cc + z * batC;
                *(__half2*)(C + (long long)grow * ldc + gcol) =
                    __floats2half2_rn(acc[i][j][0], acc[i][j][1]);
                *(__half2*)(C + (long long)(grow + 8) * ldc + gcol) =
                    __floats2half2_rn(acc[i][j][2], acc[i][j][3]);
            } else {
                float* C = (float*)Cc + z * batC;
                *(float2*)(C + (long long)grow * ldc + gcol) =
                    make_float2(acc[i][j][0], acc[i][j][1]);
                *(float2*)(C + (long long)(grow + 8) * ldc + gcol) =
                    make_float2(acc[i][j][2], acc[i][j][3]);
            }
        }
    }
}

// ===========================================================================
// y2 = y1h * wzh^T + bias, fp16 mma + ldmatrix, 64x64x32 with fused BN stats
// ===========================================================================
__global__ __launch_bounds__(128) void y2h_stats(
    const __half* __restrict__ A, const float* __restrict__ bias,
    float* __restrict__ Cc)
{
    const long long z = blockIdx.z;
    A  += z * (long long)NP_ * IC_;
    Cc += z * (long long)N_ * C_;

    const int m0 = blockIdx.x * 64;
    const int n0 = blockIdx.y * 64;
    const int tid = threadIdx.x;
    const int w = tid >> 5, lane = tid & 31;
    const int gid = lane >> 2, tig = lane & 3;
    const int wm = (w & 1) * 32, wn = (w >> 1) * 32;

    __shared__ uint32_t As[64 * FSTR];
    __shared__ uint32_t Bs[64 * FSTR];
    __shared__ float csum[64];
    __shared__ float csq [64];

    if (tid < 64) { csum[tid] = 0.f; csq[tid] = 0.f; }

    const int a_row = (lane & 7) + ((lane >> 3) & 1) * 8;
    const int a_kb  = (lane >> 4) * 16;
    const int b_row = (lane & 7) + (lane >> 4) * 8;
    const int b_kb  = ((lane >> 3) & 1) * 16;

    float acc[2][4][4];
    #pragma unroll
    for (int i = 0; i < 2; i++)
        #pragma unroll
        for (int j = 0; j < 4; j++)
            #pragma unroll
            for (int r = 0; r < 4; r++) acc[i][j][r] = 0.0f;

    for (int k0 = 0; k0 < IC_; k0 += 32) {
        #pragma unroll
        for (int it = 0; it < 2; it++) {
            int lin = tid + it * 128;
            int row = lin >> 2, k8 = (lin & 3) << 3, kw = (lin & 3) << 2;
            *(uint4*)(&As[row * FSTR + kw]) =
                *(const uint4*)(A + (long long)(m0 + row) * IC_ + k0 + k8);
            *(uint4*)(&Bs[row * FSTR + kw]) =
                *(const uint4*)(g_wzh + (long long)(n0 + row) * IC_ + k0 + k8);
        }
        __syncthreads();

        const uint32_t abase = smem_u32(As);
        const uint32_t bbase = smem_u32(Bs);
        #pragma unroll
        for (int ks = 0; ks < 2; ks++) {
            const int kb = ks * 32;
            uint32_t af[2][4];
            #pragma unroll
            for (int i = 0; i < 2; i++)
                ldsm_x4(af[i][0], af[i][1], af[i][2], af[i][3],
                        abase + (wm + i * 16 + a_row) * FSTRB + kb + a_kb);
            uint32_t bf[4][2];
            #pragma unroll
            for (int jj = 0; jj < 2; jj++)
                ldsm_x4(bf[jj * 2][0], bf[jj * 2][1], bf[jj * 2 + 1][0], bf[jj * 2 + 1][1],
                        bbase + (wn + jj * 16 + b_row) * FSTRB + kb + b_kb);
            #pragma unroll
            for (int i = 0; i < 2; i++)
                #pragma unroll
                for (int j = 0; j < 4; j++)
                    mma_f16(acc[i][j][0], acc[i][j][1], acc[i][j][2], acc[i][j][3],
                            af[i][0], af[i][1], af[i][2], af[i][3],
                            bf[j][0], bf[j][1]);
        }
        __syncthreads();
    }

    #pragma unroll
    for (int j = 0; j < 4; j++) {
        int lcol = wn + j * 8 + tig * 2;
        int gcol = n0 + lcol;
        float b0v = bias[gcol], b1v = bias[gcol + 1];
        float s0 = 0.f, q0 = 0.f, s1 = 0.f, q1 = 0.f;
        #pragma unroll
        for (int i = 0; i < 2; i++) {
            int grow = m0 + wm + i * 16 + gid;
            float v00 = acc[i][j][0] + b0v;
            float v01 = acc[i][j][1] + b1v;
            float v10 = acc[i][j][2] + b0v;
            float v11 = acc[i][j][3] + b1v;
            *(float2*)(Cc + (long long)grow * C_ + gcol)       = make_float2(v00, v01);
            *(float2*)(Cc + (long long)(grow + 8) * C_ + gcol) = make_float2(v10, v11);
            s0 += v00 + v10;  q0 += v00 * v00 + v10 * v10;
            s1 += v01 + v11;  q1 += v01 * v01 + v11 * v11;
        }
        atomicAdd(&csum[lcol],     s0);
        atomicAdd(&csq [lcol],     q0);
        atomicAdd(&csum[lcol + 1], s1);
        atomicAdd(&csq [lcol + 1], q1);
    }
    __syncthreads();
    if (tid < 64) {
        atomicAdd(&g_sum  [n0 + tid], (double)csum[tid]);
        atomicAdd(&g_sumsq[n0 + tid], (double)csq [tid]);
    }
}

// ---------------------------------------------------------------------------
// Row softmax (unchanged)
// ---------------------------------------------------------------------------
#define NF4 (N_ / 4)

__global__ __launch_bounds__(256) void softmax_rows(
    const float* __restrict__ S, __half* __restrict__ P)
{
    __shared__ float buf[N_];
    __shared__ float wredm[8];
    __shared__ float wreds[8];
    const float* row = S + (size_t)blockIdx.y * NP_ * NP_ + (size_t)blockIdx.x * NP_;
    __half* prow     = P + (size_t)blockIdx.y * NP_ * NP_ + (size_t)blockIdx.x * NP_;
    const int tid = threadIdx.x;
    const int wid = tid >> 5, lane = tid & 31;

    float m = -1e30f;
    for (int i4 = tid; i4 < NF4; i4 += 256) {
        float4 v = ((const float4*)row)[i4];
        ((float4*)buf)[i4] = v;
        m = fmaxf(fmaxf(m, fmaxf(v.x, v.y)), fmaxf(v.z, v.w));
    }
    #pragma unroll
    for (int o = 16; o > 0; o >>= 1) m = fmaxf(m, __shfl_xor_sync(~0u, m, o));
    if (lane == 0) wredm[wid] = m;
    __syncthreads();
    m = wredm[0];
    #pragma unroll
    for (int k = 1; k < 8; k++) m = fmaxf(m, wredm[k]);

    float sum = 0.f;
    for (int i4 = tid; i4 < NF4; i4 += 256) {
        float4 v = ((const float4*)buf)[i4];
        v.x = __expf(v.x - m); v.y = __expf(v.y - m);
        v.z = __expf(v.z - m); v.w = __expf(v.w - m);
        ((float4*)buf)[i4] = v;
        sum += (v.x + v.y) + (v.z + v.w);
    }
    #pragma unroll
    for (int o = 16; o > 0; o >>= 1) sum += __shfl_xor_sync(~0u, sum, o);
    if (lane == 0) wreds[wid] = sum;
    __syncthreads();
    sum = wreds[0];
    #pragma unroll
    for (int k = 1; k < 8; k++) sum += wreds[k];
    const float inv = 1.0f / sum;

    for (int i4 = tid; i4 < NF4; i4 += 256) {
        float4 v = ((const float4*)buf)[i4];
        uint2 o;
        __half2 h0 = __floats2half2_rn(v.x * inv, v.y * inv);
        __half2 h1 = __floats2half2_rn(v.z * inv, v.w * inv);
        o.x = *(uint32_t*)&h0;
        o.y = *(uint32_t*)&h1;
        ((uint2*)prow)[i4] = o;
    }
}

// ---------------------------------------------------------------------------
// BN: zero stats + final (unchanged)
// ---------------------------------------------------------------------------
__global__ void zero_stats()
{
    int t = threadIdx.x;
    g_sum[t] = 0.0;
    g_sumsq[t] = 0.0;
}

__global__ __launch_bounds__(256) void bn_final(
    const float* __restrict__ x,
    const float* __restrict__ bn_w, const float* __restrict__ bn_b,
    float* __restrict__ out)
{
    __shared__ float t[32][33];
    const int b  = blockIdx.z;
    const int c0 = blockIdx.y * 32;
    const int n0 = blockIdx.x * 32;
    const int tx = threadIdx.x, ty = threadIdx.y;

    #pragma unroll
    for (int j = 0; j < 32; j += 8) {
        int n = n0 + ty + j;
        t[ty + j][tx] = g_y2[((size_t)(b * N_ + n)) * C_ + c0 + tx];
    }
    __syncthreads();

    const double cnt = (double)ROWS_TOTAL;
    #pragma unroll
    for (int j = 0; j < 32; j += 8) {
        int c = c0 + ty + j;
        double mean = g_sum[c] / cnt;
        double var  = g_sumsq[c] / cnt - mean * mean;
        float inv = (float)rsqrt(var + 1e-5);
        float w = bn_w[c], bb = bn_b[c];
        int n = n0 + tx;
        size_t oidx = ((size_t)b * C_ + c) * (size_t)N_ + n;
        float v = t[tx][ty + j];
        out[oidx] = (v - (float)mean) * inv * w + bb + x[oidx];
    }
}

// ---------------------------------------------------------------------------
// Launch
// ---------------------------------------------------------------------------
extern "C" void kernel_launch(void* const* d_in, const int* in_sizes, int n_in,
                              void* d_out, int out_size)
{
    const float* x       = (const float*)d_in[0];
    const float* theta_w = (const float*)d_in[1];
    const float* theta_b = (const float*)d_in[2];
    const float* phi_w   = (const float*)d_in[3];
    const float* phi_b   = (const float*)d_in[4];
    const float* gw      = (const float*)d_in[5];
    const float* gb      = (const float*)d_in[6];
    const float* wz_w    = (const float*)d_in[7];
    const float* wz_b    = (const float*)d_in[8];
    const float* bn_w    = (const float*)d_in[9];
    const float* bn_b    = (const float*)d_in[10];
    float* out = (float*)d_out;

    float *S, *y2;
    __half *Qh, *Kh, *Vt, *P, *y1h;
    cudaGetSymbolAddress((void**)&Qh,  g_Qh);
    cudaGetSymbolAddress((void**)&Kh,  g_Kh);
    cudaGetSymbolAddress((void**)&Vt,  g_Vt);
    cudaGetSymbolAddress((void**)&S,   g_S);
    cudaGetSymbolAddress((void**)&P,   g_P);
    cudaGetSymbolAddress((void**)&y1h, g_y1h);
    cudaGetSymbolAddress((void**)&y2,  g_y2);

    zero_stats<<<1, 512>>>();

    conv_weights<<<(4 * IC_ * C_) / 256, 256>>>(theta_w, phi_w, gw, wz_w);
    x_to_h<<<dim3(N_ / 32, C_ / 32, B_), dim3(32, 8)>>>(x);

    // fused QKV: grid (49 m-tiles, 4 n-windows, 8 batches)
    qkv3_f16<<<dim3(N_ / 64, IC_ / 64, B_), 128>>>(
        theta_b, phi_b, gb, Qh, Kh, Vt);

    gemm_f16<false><<<dim3(NP_ / 128, NP_ / 128, B_), 128>>>(Qh, Kh, S,
        IC_, IC_, IC_, NP_,
        (long long)NP_ * IC_, (long long)NP_ * IC_, (long long)NP_ * NP_);

    softmax_rows<<<dim3(N_, B_), 256>>>(S, P);

    gemm_f16<true><<<dim3(NP_ / 128, IC_ / 128, B_), 128>>>(P, Vt, y1h,
        N_, NP_, NP_, IC_,
        (long long)NP_ * NP_, (long long)IC_ * NP_, (long long)NP_ * IC_);

    y2h_stats<<<dim3(N_ / 64, C_ / 64, B_), 128>>>(y1h, wz_b, y2);

    bn_final<<<dim3(N_ / 32, C_ / 32, B_), dim3(32, 8)>>>(x, bn_w, bn_b, out);
}

// round 14
// speedup vs baseline: 1.1018x; 1.1018x over previous
#include <cuda_runtime.h>
#include <cuda_fp16.h>
#include <math.h>
#include <stdint.h>

// Problem constants
#define B_   8
#define C_   512
#define N_   3136   // 56*56
#define NP_  3200   // N padded to multiple of 128
#define IC_  256
#define ROWS_TOTAL (B_ * N_)   // 25088

// ---------------------------------------------------------------------------
// Scratch
// ---------------------------------------------------------------------------
__device__ __half g_xh [(size_t)B_ * NP_ * C_];   // x fp16 transposed [token][c]
__device__ __half g_Wh [(size_t)3 * IC_ * C_];    // theta/phi/g weights fp16
__device__ __half g_wzh[(size_t)C_ * IC_];        // wz fp16
__device__ __half g_Qh [(size_t)B_ * NP_ * IC_];  // Q fp16 [token][i]
__device__ __half g_Kh [(size_t)B_ * NP_ * IC_];  // K fp16 [token][i]
__device__ __half g_Vt [(size_t)B_ * IC_ * NP_];  // V fp16 transposed [i][token]
__device__ float  g_S  [(size_t)B_ * NP_ * NP_];  // logits fp32
__device__ __half g_P  [(size_t)B_ * NP_ * NP_];  // softmax probs fp16
__device__ __half g_y1h[(size_t)B_ * NP_ * IC_];  // attention out fp16
__device__ float  g_y2 [(size_t)B_ * N_ * C_];
__device__ double g_sum[C_];
__device__ double g_sumsq[C_];

// ---------------------------------------------------------------------------
// mma / ldmatrix / cp.async helpers
// ---------------------------------------------------------------------------
__device__ __forceinline__ void mma_f16(float& d0, float& d1, float& d2, float& d3,
                                        uint32_t a0, uint32_t a1, uint32_t a2, uint32_t a3,
                                        uint32_t b0, uint32_t b1) {
    asm volatile(
        "mma.sync.aligned.m16n8k16.row.col.f32.f16.f16.f32 "
        "{%0,%1,%2,%3}, {%4,%5,%6,%7}, {%8,%9}, {%0,%1,%2,%3};\n"
        : "+f"(d0), "+f"(d1), "+f"(d2), "+f"(d3)
        : "r"(a0), "r"(a1), "r"(a2), "r"(a3), "r"(b0), "r"(b1));
}
__device__ __forceinline__ void ldsm_x4(uint32_t& r0, uint32_t& r1, uint32_t& r2, uint32_t& r3,
                                        uint32_t addr) {
    asm volatile("ldmatrix.sync.aligned.m8n8.x4.shared.b16 {%0,%1,%2,%3}, [%4];"
                 : "=r"(r0), "=r"(r1), "=r"(r2), "=r"(r3) : "r"(addr));
}
__device__ __forceinline__ void ldsm_x2(uint32_t& r0, uint32_t& r1, uint32_t addr) {
    asm volatile("ldmatrix.sync.aligned.m8n8.x2.shared.b16 {%0,%1}, [%2];"
                 : "=r"(r0), "=r"(r1) : "r"(addr));
}
__device__ __forceinline__ uint32_t smem_u32(const void* p) {
    return (uint32_t)__cvta_generic_to_shared(p);
}
__device__ __forceinline__ void cp_async16(uint32_t saddr, const void* gptr) {
    asm volatile("cp.async.cg.shared.global [%0], [%1], 16;" :: "r"(saddr), "l"(gptr));
}
__device__ __forceinline__ void cp_commit() {
    asm volatile("cp.async.commit_group;");
}
__device__ __forceinline__ void cp_wait0() {
    asm volatile("cp.async.wait_group 0;");
}

constexpr int FSTR = 20;       // 20 words = 80 bytes per SMEM row (32 data halves + pad)
constexpr int FSTRB = 80;      // bytes

// ---------------------------------------------------------------------------
// Prep kernels
// ---------------------------------------------------------------------------
__global__ void conv_weights(const float* __restrict__ tw, const float* __restrict__ pw,
                             const float* __restrict__ gw, const float* __restrict__ wz)
{
    const int WSZ = IC_ * C_;            // 131072
    int idx = blockIdx.x * 256 + threadIdx.x;
    if (idx < 3 * WSZ) {
        const float* src = (idx < WSZ) ? tw : (idx < 2 * WSZ ? pw : gw);
        g_Wh[idx] = __float2half_rn(src[idx % WSZ]);
    } else {
        int off = idx - 3 * WSZ;
        g_wzh[off] = __float2half_rn(wz[off]);
    }
}

__global__ __launch_bounds__(256) void x_to_h(const float* __restrict__ x)
{
    __shared__ float t[32][33];
    const int b  = blockIdx.z;
    const int n0 = blockIdx.x * 32;
    const int c0 = blockIdx.y * 32;
    const float* xb = x + (size_t)b * C_ * N_;
    __half* xh = g_xh + (size_t)b * NP_ * C_;
    const int tx = threadIdx.x, ty = threadIdx.y;

    #pragma unroll
    for (int j = 0; j < 32; j += 8)
        t[ty + j][tx] = xb[(size_t)(c0 + ty + j) * N_ + n0 + tx];
    __syncthreads();
    #pragma unroll
    for (int j = 0; j < 32; j += 8)
        xh[(size_t)(n0 + ty + j) * C_ + c0 + tx] = __float2half_rn(t[tx][ty + j]);
}

// ===========================================================================
// Fused QKV: fp16 mma + ldmatrix + cp.async, 64(m) x 64(n) x 32 double-buffered.
// 256 threads, 8 warps in n (warp tile 64x8 per output matrix). R11 config.
// ===========================================================================
__global__ __launch_bounds__(256) void qkv3_f16(
    const float* __restrict__ tb, const float* __restrict__ pb,
    const float* __restrict__ gb,
    __half* __restrict__ Q, __half* __restrict__ K, __half* __restrict__ Vt)
{
    const long long z = blockIdx.z;
    const __half* xh = g_xh + z * (long long)NP_ * C_;
    Q  += z * (long long)NP_ * IC_;
    K  += z * (long long)NP_ * IC_;
    Vt += z * (long long)IC_ * NP_;

    const int m0 = blockIdx.x * 64;
    const int n0 = blockIdx.y * 64;
    const int tid = threadIdx.x;
    const int w = tid >> 5, lane = tid & 31;
    const int gid = lane >> 2, tig = lane & 3;
    const int wn = w * 8;

    __shared__ uint32_t Ah[2][64 * FSTR];
    __shared__ uint32_t Bh[2][192 * FSTR];

    const int a_row = (lane & 7) + ((lane >> 3) & 1) * 8;
    const int a_kb  = (lane >> 4) * 16;
    const int b_row = (lane & 7);
    const int b_kb  = (((lane & 15) >> 3) & 1) * 16;

    float acc[3][4][4];
    #pragma unroll
    for (int s = 0; s < 3; s++)
        #pragma unroll
        for (int i = 0; i < 4; i++)
            #pragma unroll
            for (int r = 0; r < 4; r++) acc[s][i][r] = 0.0f;

    // cp.async tile loader: A 1x16B/thread, B 3x16B/thread
    auto aload = [&](int k0, int b) {
        {
            int row = tid >> 2, k8 = (tid & 3) << 3, kw = (tid & 3) << 2;
            cp_async16(smem_u32(&Ah[b][row * FSTR + kw]),
                       xh + (long long)(m0 + row) * C_ + k0 + k8);
        }
        #pragma unroll
        for (int it = 0; it < 3; it++) {
            int lin = tid + it * 256;
            int brow = lin >> 2, k8 = (lin & 3) << 3, kw = (lin & 3) << 2;
            int s = brow >> 6, wr = brow & 63;
            cp_async16(smem_u32(&Bh[b][brow * FSTR + kw]),
                       g_Wh + ((long long)s * IC_ + n0 + wr) * C_ + k0 + k8);
        }
    };

    aload(0, 0); cp_commit(); cp_wait0(); __syncthreads();
    int buf = 0;
    for (int k0 = 0; k0 < C_; k0 += 32) {
        const bool nxt = (k0 + 32 < C_);
        if (nxt) { aload(k0 + 32, buf ^ 1); cp_commit(); }

        const uint32_t abase = smem_u32(Ah[buf]);
        const uint32_t bbase = smem_u32(Bh[buf]);
        #pragma unroll
        for (int ks = 0; ks < 2; ks++) {
            const int kb = ks * 32;
            uint32_t af[4][4];
            #pragma unroll
            for (int i = 0; i < 4; i++)
                ldsm_x4(af[i][0], af[i][1], af[i][2], af[i][3],
                        abase + (i * 16 + a_row) * FSTRB + kb + a_kb);
            #pragma unroll
            for (int s = 0; s < 3; s++) {
                uint32_t b0, b1;
                ldsm_x2(b0, b1,
                        bbase + (s * 64 + wn + b_row) * FSTRB + kb + b_kb);
                #pragma unroll
                for (int i = 0; i < 4; i++)
                    mma_f16(acc[s][i][0], acc[s][i][1], acc[s][i][2], acc[s][i][3],
                            af[i][0], af[i][1], af[i][2], af[i][3], b0, b1);
            }
        }
        if (nxt) { cp_wait0(); __syncthreads(); buf ^= 1; }
    }

    const int gcol = n0 + wn + tig * 2;
    const float tb0 = tb[gcol], tb1 = tb[gcol + 1];
    const float pb0 = pb[gcol], pb1 = pb[gcol + 1];
    const float gb0 = gb[gcol], gb1 = gb[gcol + 1];
    #pragma unroll
    for (int i = 0; i < 4; i++) {
        int grow = m0 + i * 16 + gid;
        *(__half2*)(Q + (long long)grow * IC_ + gcol) =
            __floats2half2_rn(acc[0][i][0] + tb0, acc[0][i][1] + tb1);
        *(__half2*)(Q + (long long)(grow + 8) * IC_ + gcol) =
            __floats2half2_rn(acc[0][i][2] + tb0, acc[0][i][3] + tb1);
        *(__half2*)(K + (long long)grow * IC_ + gcol) =
            __floats2half2_rn(acc[1][i][0] + pb0, acc[1][i][1] + pb1);
        *(__half2*)(K + (long long)(grow + 8) * IC_ + gcol) =
            __floats2half2_rn(acc[1][i][2] + pb0, acc[1][i][3] + pb1);
        Vt[(long long)gcol       * NP_ + grow]     = __float2half_rn(acc[2][i][0] + gb0);
        Vt[(long long)(gcol + 1) * NP_ + grow]     = __float2half_rn(acc[2][i][1] + gb1);
        Vt[(long long)gcol       * NP_ + grow + 8] = __float2half_rn(acc[2][i][2] + gb0);
        Vt[(long long)(gcol + 1) * NP_ + grow + 8] = __float2half_rn(acc[2][i][3] + gb1);
    }
}

// ===========================================================================
// Generic fp16 mma GEMM + ldmatrix + cp.async, 128x128x32 double-buffered.
// 256 threads, 8 warps (2m x 4n), warp tile 64x32. R11 config.
// ===========================================================================
template<bool HALF_OUT>
__global__ __launch_bounds__(256) void gemm_f16(
    const __half* __restrict__ A, const __half* __restrict__ Bm,
    void* __restrict__ Cc,
    int K, int sA, int sB, int ldc,
    long long batA, long long batB, long long batC)
{
    const long long z = blockIdx.z;
    A  += z * batA;
    Bm += z * batB;

    const int m0 = blockIdx.x * 128;
    const int n0 = blockIdx.y * 128;
    const int tid = threadIdx.x;
    const int w = tid >> 5, lane = tid & 31;
    const int gid = lane >> 2, tig = lane & 3;
    const int wm = (w & 1) * 64, wn = (w >> 1) * 32;

    __shared__ uint32_t As[2][128 * FSTR];
    __shared__ uint32_t Bs[2][128 * FSTR];

    const int a_row = (lane & 7) + ((lane >> 3) & 1) * 8;
    const int a_kb  = (lane >> 4) * 16;
    const int b_row = (lane & 7) + (lane >> 4) * 8;
    const int b_kb  = ((lane >> 3) & 1) * 16;

    float acc[4][4][4];
    #pragma unroll
    for (int i = 0; i < 4; i++)
        #pragma unroll
        for (int j = 0; j < 4; j++)
            #pragma unroll
            for (int r = 0; r < 4; r++) acc[i][j][r] = 0.0f;

    auto aload = [&](int k0, int b) {
        #pragma unroll
        for (int it = 0; it < 2; it++) {
            int lin = tid + it * 256;
            int row = lin >> 2, k8 = (lin & 3) << 3, kw = (lin & 3) << 2;
            cp_async16(smem_u32(&As[b][row * FSTR + kw]),
                       A + (long long)(m0 + row) * sA + k0 + k8);
            cp_async16(smem_u32(&Bs[b][row * FSTR + kw]),
                       Bm + (long long)(n0 + row) * sB + k0 + k8);
        }
    };

    aload(0, 0); cp_commit(); cp_wait0(); __syncthreads();
    int buf = 0;
    for (int k0 = 0; k0 < K; k0 += 32) {
        const bool nxt = (k0 + 32 < K);
        if (nxt) { aload(k0 + 32, buf ^ 1); cp_commit(); }

        const uint32_t abase = smem_u32(As[buf]);
        const uint32_t bbase = smem_u32(Bs[buf]);
        #pragma unroll
        for (int ks = 0; ks < 2; ks++) {
            const int kb = ks * 32;
            uint32_t af[4][4];
            #pragma unroll
            for (int i = 0; i < 4; i++)
                ldsm_x4(af[i][0], af[i][1], af[i][2], af[i][3],
                        abase + (wm + i * 16 + a_row) * FSTRB + kb + a_kb);
            uint32_t bf[4][2];
            #pragma unroll
            for (int jj = 0; jj < 2; jj++)
                ldsm_x4(bf[jj * 2][0], bf[jj * 2][1], bf[jj * 2 + 1][0], bf[jj * 2 + 1][1],
                        bbase + (wn + jj * 16 + b_row) * FSTRB + kb + b_kb);
            #pragma unroll
            for (int i = 0; i < 4; i++)
                #pragma unroll
                for (int j = 0; j < 4; j++)
                    mma_f16(acc[i][j][0], acc[i][j][1], acc[i][j][2], acc[i][j][3],
                            af[i][0], af[i][1], af[i][2], af[i][3],
                            bf[j][0], bf[j][1]);
        }
        if (nxt) { cp_wait0(); __syncthreads(); buf ^= 1; }
    }

    #pragma unroll
    for (int i = 0; i < 4; i++) {
        int grow = m0 + wm + i * 16 + gid;
        #pragma unroll
        for (int j = 0; j < 4; j++) {
            int gcol = n0 + wn + j * 8 + tig * 2;
            if (HALF_OUT) {
                __half* C = (__half*)Cc + z * batC;
                *(__half2*)(C + (long long)grow * ldc + gcol) =
                    __floats2half2_rn(acc[i][j][0], acc[i][j][1]);
                *(__half2*)(C + (long long)(grow + 8) * ldc + gcol) =
                    __floats2half2_rn(acc[i][j][2], acc[i][j][3]);
            } else {
                float* C = (float*)Cc + z * batC;
                *(float2*)(C + (long long)grow * ldc + gcol) =
                    make_float2(acc[i][j][0], acc[i][j][1]);
                *(float2*)(C + (long long)(grow + 8) * ldc + gcol) =
                    make_float2(acc[i][j][2], acc[i][j][3]);
            }
        }
    }
}

// ===========================================================================
// y2 = y1h * wzh^T + bias, fp16 mma + ldmatrix, 64x64x32 with fused BN stats
// ===========================================================================
__global__ __launch_bounds__(128) void y2h_stats(
    const __half* __restrict__ A, const float* __restrict__ bias,
    float* __restrict__ Cc)
{
    const long long z = blockIdx.z;
    A  += z * (long long)NP_ * IC_;
    Cc += z * (long long)N_ * C_;

    const int m0 = blockIdx.x * 64;
    const int n0 = blockIdx.y * 64;
    const int tid = threadIdx.x;
    const int w = tid >> 5, lane = tid & 31;
    const int gid = lane >> 2, tig = lane & 3;
    const int wm = (w & 1) * 32, wn = (w >> 1) * 32;

    __shared__ uint32_t As[64 * FSTR];
    __shared__ uint32_t Bs[64 * FSTR];
    __shared__ float csum[64];
    __shared__ float csq [64];

    if (tid < 64) { csum[tid] = 0.f; csq[tid] = 0.f; }

    const int a_row = (lane & 7) + ((lane >> 3) & 1) * 8;
    const int a_kb  = (lane >> 4) * 16;
    const int b_row = (lane & 7) + (lane >> 4) * 8;
    const int b_kb  = ((lane >> 3) & 1) * 16;

    float acc[2][4][4];
    #pragma unroll
    for (int i = 0; i < 2; i++)
        #pragma unroll
        for (int j = 0; j < 4; j++)
            #pragma unroll
            for (int r = 0; r < 4; r++) acc[i][j][r] = 0.0f;

    for (int k0 = 0; k0 < IC_; k0 += 32) {
        #pragma unroll
        for (int it = 0; it < 2; it++) {
            int lin = tid + it * 128;
            int row = lin >> 2, k8 = (lin & 3) << 3, kw = (lin & 3) << 2;
            *(uint4*)(&As[row * FSTR + kw]) =
                *(const uint4*)(A + (long long)(m0 + row) * IC_ + k0 + k8);
            *(uint4*)(&Bs[row * FSTR + kw]) =
                *(const uint4*)(g_wzh + (long long)(n0 + row) * IC_ + k0 + k8);
        }
        __syncthreads();

        const uint32_t abase = smem_u32(As);
        const uint32_t bbase = smem_u32(Bs);
        #pragma unroll
        for (int ks = 0; ks < 2; ks++) {
            const int kb = ks * 32;
            uint32_t af[2][4];
            #pragma unroll
            for (int i = 0; i < 2; i++)
                ldsm_x4(af[i][0], af[i][1], af[i][2], af[i][3],
                        abase + (wm + i * 16 + a_row) * FSTRB + kb + a_kb);
            uint32_t bf[4][2];
            #pragma unroll
            for (int jj = 0; jj < 2; jj++)
                ldsm_x4(bf[jj * 2][0], bf[jj * 2][1], bf[jj * 2 + 1][0], bf[jj * 2 + 1][1],
                        bbase + (wn + jj * 16 + b_row) * FSTRB + kb + b_kb);
            #pragma unroll
            for (int i = 0; i < 2; i++)
                #pragma unroll
                for (int j = 0; j < 4; j++)
                    mma_f16(acc[i][j][0], acc[i][j][1], acc[i][j][2], acc[i][j][3],
                            af[i][0], af[i][1], af[i][2], af[i][3],
                            bf[j][0], bf[j][1]);
        }
        __syncthreads();
    }

    #pragma unroll
    for (int j = 0; j < 4; j++) {
        int lcol = wn + j * 8 + tig * 2;
        int gcol = n0 + lcol;
        float b0v = bias[gcol], b1v = bias[gcol + 1];
        float s0 = 0.f, q0 = 0.f, s1 = 0.f, q1 = 0.f;
        #pragma unroll
        for (int i = 0; i < 2; i++) {
            int grow = m0 + wm + i * 16 + gid;
            float v00 = acc[i][j][0] + b0v;
            float v01 = acc[i][j][1] + b1v;
            float v10 = acc[i][j][2] + b0v;
            float v11 = acc[i][j][3] + b1v;
            *(float2*)(Cc + (long long)grow * C_ + gcol)       = make_float2(v00, v01);
            *(float2*)(Cc + (long long)(grow + 8) * C_ + gcol) = make_float2(v10, v11);
            s0 += v00 + v10;  q0 += v00 * v00 + v10 * v10;
            s1 += v01 + v11;  q1 += v01 * v01 + v11 * v11;
        }
        atomicAdd(&csum[lcol],     s0);
        atomicAdd(&csq [lcol],     q0);
        atomicAdd(&csum[lcol + 1], s1);
        atomicAdd(&csq [lcol + 1], q1);
    }
    __syncthreads();
    if (tid < 64) {
        atomicAdd(&g_sum  [n0 + tid], (double)csum[tid]);
        atomicAdd(&g_sumsq[n0 + tid], (double)csq [tid]);
    }
}

// ---------------------------------------------------------------------------
// Row softmax (unchanged)
// ---------------------------------------------------------------------------
#define NF4 (N_ / 4)

__global__ __launch_bounds__(256) void softmax_rows(
    const float* __restrict__ S, __half* __restrict__ P)
{
    __shared__ float buf[N_];
    __shared__ float wredm[8];
    __shared__ float wreds[8];
    const float* row = S + (size_t)blockIdx.y * NP_ * NP_ + (size_t)blockIdx.x * NP_;
    __half* prow     = P + (size_t)blockIdx.y * NP_ * NP_ + (size_t)blockIdx.x * NP_;
    const int tid = threadIdx.x;
    const int wid = tid >> 5, lane = tid & 31;

    float m = -1e30f;
    for (int i4 = tid; i4 < NF4; i4 += 256) {
        float4 v = ((const float4*)row)[i4];
        ((float4*)buf)[i4] = v;
        m = fmaxf(fmaxf(m, fmaxf(v.x, v.y)), fmaxf(v.z, v.w));
    }
    #pragma unroll
    for (int o = 16; o > 0; o >>= 1) m = fmaxf(m, __shfl_xor_sync(~0u, m, o));
    if (lane == 0) wredm[wid] = m;
    __syncthreads();
    m = wredm[0];
    #pragma unroll
    for (int k = 1; k < 8; k++) m = fmaxf(m, wredm[k]);

    float sum = 0.f;
    for (int i4 = tid; i4 < NF4; i4 += 256) {
        float4 v = ((const float4*)buf)[i4];
        v.x = __expf(v.x - m); v.y = __expf(v.y - m);
        v.z = __expf(v.z - m); v.w = __expf(v.w - m);
        ((float4*)buf)[i4] = v;
        sum += (v.x + v.y) + (v.z + v.w);
    }
    #pragma unroll
    for (int o = 16; o > 0; o >>= 1) sum += __shfl_xor_sync(~0u, sum, o);
    if (lane == 0) wreds[wid] = sum;
    __syncthreads();
    sum = wreds[0];
    #pragma unroll
    for (int k = 1; k < 8; k++) sum += wreds[k];
    const float inv = 1.0f / sum;

    for (int i4 = tid; i4 < NF4; i4 += 256) {
        float4 v = ((const float4*)buf)[i4];
        uint2 o;
        __half2 h0 = __floats2half2_rn(v.x * inv, v.y * inv);
        __half2 h1 = __floats2half2_rn(v.z * inv, v.w * inv);
        o.x = *(uint32_t*)&h0;
        o.y = *(uint32_t*)&h1;
        ((uint2*)prow)[i4] = o;
    }
}

// ---------------------------------------------------------------------------
// BN: zero stats + final (unchanged)
// ---------------------------------------------------------------------------
__global__ void zero_stats()
{
    int t = threadIdx.x;
    g_sum[t] = 0.0;
    g_sumsq[t] = 0.0;
}

__global__ __launch_bounds__(256) void bn_final(
    const float* __restrict__ x,
    const float* __restrict__ bn_w, const float* __restrict__ bn_b,
    float* __restrict__ out)
{
    __shared__ float t[32][33];
    const int b  = blockIdx.z;
    const int c0 = blockIdx.y * 32;
    const int n0 = blockIdx.x * 32;
    const int tx = threadIdx.x, ty = threadIdx.y;

    #pragma unroll
    for (int j = 0; j < 32; j += 8) {
        int n = n0 + ty + j;
        t[ty + j][tx] = g_y2[((size_t)(b * N_ + n)) * C_ + c0 + tx];
    }
    __syncthreads();

    const double cnt = (double)ROWS_TOTAL;
    #pragma unroll
    for (int j = 0; j < 32; j += 8) {
        int c = c0 + ty + j;
        double mean = g_sum[c] / cnt;
        double var  = g_sumsq[c] / cnt - mean * mean;
        float inv = (float)rsqrt(var + 1e-5);
        float w = bn_w[c], bb = bn_b[c];
        int n = n0 + tx;
        size_t oidx = ((size_t)b * C_ + c) * (size_t)N_ + n;
        float v = t[tx][ty + j];
        out[oidx] = (v - (float)mean) * inv * w + bb + x[oidx];
    }
}

// ---------------------------------------------------------------------------
// Launch
// ---------------------------------------------------------------------------
extern "C" void kernel_launch(void* const* d_in, const int* in_sizes, int n_in,
                              void* d_out, int out_size)
{
    const float* x       = (const float*)d_in[0];
    const float* theta_w = (const float*)d_in[1];
    const float* theta_b = (const float*)d_in[2];
    const float* phi_w   = (const float*)d_in[3];
    const float* phi_b   = (const float*)d_in[4];
    const float* gw      = (const float*)d_in[5];
    const float* gb      = (const float*)d_in[6];
    const float* wz_w    = (const float*)d_in[7];
    const float* wz_b    = (const float*)d_in[8];
    const float* bn_w    = (const float*)d_in[9];
    const float* bn_b    = (const float*)d_in[10];
    float* out = (float*)d_out;

    float *S, *y2;
    __half *Qh, *Kh, *Vt, *P, *y1h;
    cudaGetSymbolAddress((void**)&Qh,  g_Qh);
    cudaGetSymbolAddress((void**)&Kh,  g_Kh);
    cudaGetSymbolAddress((void**)&Vt,  g_Vt);
    cudaGetSymbolAddress((void**)&S,   g_S);
    cudaGetSymbolAddress((void**)&P,   g_P);
    cudaGetSymbolAddress((void**)&y1h, g_y1h);
    cudaGetSymbolAddress((void**)&y2,  g_y2);

    zero_stats<<<1, 512>>>();

    conv_weights<<<(4 * IC_ * C_) / 256, 256>>>(theta_w, phi_w, gw, wz_w);
    x_to_h<<<dim3(N_ / 32, C_ / 32, B_), dim3(32, 8)>>>(x);

    qkv3_f16<<<dim3(N_ / 64, IC_ / 64, B_), 256>>>(
        theta_b, phi_b, gb, Qh, Kh, Vt);

    gemm_f16<false><<<dim3(NP_ / 128, NP_ / 128, B_), 256>>>(Qh, Kh, S,
        IC_, IC_, IC_, NP_,
        (long long)NP_ * IC_, (long long)NP_ * IC_, (long long)NP_ * NP_);

    softmax_rows<<<dim3(N_, B_), 256>>>(S, P);

    gemm_f16<true><<<dim3(NP_ / 128, IC_ / 128, B_), 256>>>(P, Vt, y1h,
        N_, NP_, NP_, IC_,
        (long long)NP_ * NP_, (long long)IC_ * NP_, (long long)NP_ * IC_);

    y2h_stats<<<dim3(N_ / 64, C_ / 64, B_), 128>>>(y1h, wz_b, y2);

    bn_final<<<dim3(N_ / 32, C_ / 32, B_), dim3(32, 8)>>>(x, bn_w, bn_b, out);
}

// round 15
// speedup vs baseline: 1.1690x; 1.0609x over previous
#include <cuda_runtime.h>
#include <cuda_fp16.h>
#include <math.h>
#include <stdint.h>

// Problem constants
#define B_   8
#define C_   512
#define N_   3136   // 56*56
#define NP_  3200   // N padded to multiple of 128
#define IC_  256
#define ROWS_TOTAL (B_ * N_)   // 25088

// ---------------------------------------------------------------------------
// Scratch
// ---------------------------------------------------------------------------
__device__ __half g_xh [(size_t)B_ * NP_ * C_];   // x fp16 transposed [token][c]
__device__ __half g_Wh [(size_t)3 * IC_ * C_];    // theta/phi/g weights fp16
__device__ __half g_wzh[(size_t)C_ * IC_];        // wz fp16
__device__ __half g_Qh [(size_t)B_ * NP_ * IC_];  // Q fp16 [token][i]
__device__ __half g_Kh [(size_t)B_ * NP_ * IC_];  // K fp16 [token][i]
__device__ __half g_Vt [(size_t)B_ * IC_ * NP_];  // V fp16 transposed [i][token]
__device__ __half g_y1h[(size_t)B_ * NP_ * IC_];  // attention out fp16
__device__ float  g_y2 [(size_t)B_ * N_ * C_];
__device__ double g_sum[C_];
__device__ double g_sumsq[C_];

// ---------------------------------------------------------------------------
// mma / ldmatrix / cp.async helpers
// ---------------------------------------------------------------------------
__device__ __forceinline__ void mma_f16(float& d0, float& d1, float& d2, float& d3,
                                        uint32_t a0, uint32_t a1, uint32_t a2, uint32_t a3,
                                        uint32_t b0, uint32_t b1) {
    asm volatile(
        "mma.sync.aligned.m16n8k16.row.col.f32.f16.f16.f32 "
        "{%0,%1,%2,%3}, {%4,%5,%6,%7}, {%8,%9}, {%0,%1,%2,%3};\n"
        : "+f"(d0), "+f"(d1), "+f"(d2), "+f"(d3)
        : "r"(a0), "r"(a1), "r"(a2), "r"(a3), "r"(b0), "r"(b1));
}
__device__ __forceinline__ void ldsm_x4(uint32_t& r0, uint32_t& r1, uint32_t& r2, uint32_t& r3,
                                        uint32_t addr) {
    asm volatile("ldmatrix.sync.aligned.m8n8.x4.shared.b16 {%0,%1,%2,%3}, [%4];"
                 : "=r"(r0), "=r"(r1), "=r"(r2), "=r"(r3) : "r"(addr));
}
__device__ __forceinline__ void ldsm_x2(uint32_t& r0, uint32_t& r1, uint32_t addr) {
    asm volatile("ldmatrix.sync.aligned.m8n8.x2.shared.b16 {%0,%1}, [%2];"
                 : "=r"(r0), "=r"(r1) : "r"(addr));
}
__device__ __forceinline__ uint32_t smem_u32(const void* p) {
    return (uint32_t)__cvta_generic_to_shared(p);
}
__device__ __forceinline__ void cp_async16(uint32_t saddr, const void* gptr) {
    asm volatile("cp.async.cg.shared.global [%0], [%1], 16;" :: "r"(saddr), "l"(gptr));
}
__device__ __forceinline__ void cp_commit() {
    asm volatile("cp.async.commit_group;");
}
__device__ __forceinline__ void cp_wait0() {
    asm volatile("cp.async.wait_group 0;");
}

constexpr int FSTR = 20;       // 20 words = 80 bytes per SMEM row (32 data halves + pad)
constexpr int FSTRB = 80;      // bytes

// ---------------------------------------------------------------------------
// Prep kernels
// ---------------------------------------------------------------------------
__global__ void conv_weights(const float* __restrict__ tw, const float* __restrict__ pw,
                             const float* __restrict__ gw, const float* __restrict__ wz)
{
    const int WSZ = IC_ * C_;            // 131072
    int idx = blockIdx.x * 256 + threadIdx.x;
    if (idx < 3 * WSZ) {
        const float* src = (idx < WSZ) ? tw : (idx < 2 * WSZ ? pw : gw);
        g_Wh[idx] = __float2half_rn(src[idx % WSZ]);
    } else {
        int off = idx - 3 * WSZ;
        g_wzh[off] = __float2half_rn(wz[off]);
    }
}

__global__ __launch_bounds__(256) void x_to_h(const float* __restrict__ x)
{
    __shared__ float t[32][33];
    const int b  = blockIdx.z;
    const int n0 = blockIdx.x * 32;
    const int c0 = blockIdx.y * 32;
    const float* xb = x + (size_t)b * C_ * N_;
    __half* xh = g_xh + (size_t)b * NP_ * C_;
    const int tx = threadIdx.x, ty = threadIdx.y;

    #pragma unroll
    for (int j = 0; j < 32; j += 8)
        t[ty + j][tx] = xb[(size_t)(c0 + ty + j) * N_ + n0 + tx];
    __syncthreads();
    #pragma unroll
    for (int j = 0; j < 32; j += 8)
        xh[(size_t)(n0 + ty + j) * C_ + c0 + tx] = __float2half_rn(t[tx][ty + j]);
}

// ===========================================================================
// Fused QKV (unchanged R14: cp.async + ldmatrix, 64x64x32)
// ===========================================================================
__global__ __launch_bounds__(256) void qkv3_f16(
    const float* __restrict__ tb, const float* __restrict__ pb,
    const float* __restrict__ gb,
    __half* __restrict__ Q, __half* __restrict__ K, __half* __restrict__ Vt)
{
    const long long z = blockIdx.z;
    const __half* xh = g_xh + z * (long long)NP_ * C_;
    Q  += z * (long long)NP_ * IC_;
    K  += z * (long long)NP_ * IC_;
    Vt += z * (long long)IC_ * NP_;

    const int m0 = blockIdx.x * 64;
    const int n0 = blockIdx.y * 64;
    const int tid = threadIdx.x;
    const int w = tid >> 5, lane = tid & 31;
    const int gid = lane >> 2, tig = lane & 3;
    const int wn = w * 8;

    __shared__ uint32_t Ah[2][64 * FSTR];
    __shared__ uint32_t Bh[2][192 * FSTR];

    const int a_row = (lane & 7) + ((lane >> 3) & 1) * 8;
    const int a_kb  = (lane >> 4) * 16;
    const int b_row = (lane & 7);
    const int b_kb  = (((lane & 15) >> 3) & 1) * 16;

    float acc[3][4][4];
    #pragma unroll
    for (int s = 0; s < 3; s++)
        #pragma unroll
        for (int i = 0; i < 4; i++)
            #pragma unroll
            for (int r = 0; r < 4; r++) acc[s][i][r] = 0.0f;

    auto aload = [&](int k0, int b) {
        {
            int row = tid >> 2, k8 = (tid & 3) << 3, kw = (tid & 3) << 2;
            cp_async16(smem_u32(&Ah[b][row * FSTR + kw]),
                       xh + (long long)(m0 + row) * C_ + k0 + k8);
        }
        #pragma unroll
        for (int it = 0; it < 3; it++) {
            int lin = tid + it * 256;
            int brow = lin >> 2, k8 = (lin & 3) << 3, kw = (lin & 3) << 2;
            int s = brow >> 6, wr = brow & 63;
            cp_async16(smem_u32(&Bh[b][brow * FSTR + kw]),
                       g_Wh + ((long long)s * IC_ + n0 + wr) * C_ + k0 + k8);
        }
    };

    aload(0, 0); cp_commit(); cp_wait0(); __syncthreads();
    int buf = 0;
    for (int k0 = 0; k0 < C_; k0 += 32) {
        const bool nxt = (k0 + 32 < C_);
        if (nxt) { aload(k0 + 32, buf ^ 1); cp_commit(); }

        const uint32_t abase = smem_u32(Ah[buf]);
        const uint32_t bbase = smem_u32(Bh[buf]);
        #pragma unroll
        for (int ks = 0; ks < 2; ks++) {
            const int kb = ks * 32;
            uint32_t af[4][4];
            #pragma unroll
            for (int i = 0; i < 4; i++)
                ldsm_x4(af[i][0], af[i][1], af[i][2], af[i][3],
                        abase + (i * 16 + a_row) * FSTRB + kb + a_kb);
            #pragma unroll
            for (int s = 0; s < 3; s++) {
                uint32_t b0, b1;
                ldsm_x2(b0, b1,
                        bbase + (s * 64 + wn + b_row) * FSTRB + kb + b_kb);
                #pragma unroll
                for (int i = 0; i < 4; i++)
                    mma_f16(acc[s][i][0], acc[s][i][1], acc[s][i][2], acc[s][i][3],
                            af[i][0], af[i][1], af[i][2], af[i][3], b0, b1);
            }
        }
        if (nxt) { cp_wait0(); __syncthreads(); buf ^= 1; }
    }

    const int gcol = n0 + wn + tig * 2;
    const float tb0 = tb[gcol], tb1 = tb[gcol + 1];
    const float pb0 = pb[gcol], pb1 = pb[gcol + 1];
    const float gb0 = gb[gcol], gb1 = gb[gcol + 1];
    #pragma unroll
    for (int i = 0; i < 4; i++) {
        int grow = m0 + i * 16 + gid;
        *(__half2*)(Q + (long long)grow * IC_ + gcol) =
            __floats2half2_rn(acc[0][i][0] + tb0, acc[0][i][1] + tb1);
        *(__half2*)(Q + (long long)(grow + 8) * IC_ + gcol) =
            __floats2half2_rn(acc[0][i][2] + tb0, acc[0][i][3] + tb1);
        *(__half2*)(K + (long long)grow * IC_ + gcol) =
            __floats2half2_rn(acc[1][i][0] + pb0, acc[1][i][1] + pb1);
        *(__half2*)(K + (long long)(grow + 8) * IC_ + gcol) =
            __floats2half2_rn(acc[1][i][2] + pb0, acc[1][i][3] + pb1);
        Vt[(long long)gcol       * NP_ + grow]     = __float2half_rn(acc[2][i][0] + gb0);
        Vt[(long long)(gcol + 1) * NP_ + grow]     = __float2half_rn(acc[2][i][1] + gb1);
        Vt[(long long)gcol       * NP_ + grow + 8] = __float2half_rn(acc[2][i][2] + gb0);
        Vt[(long long)(gcol + 1) * NP_ + grow + 8] = __float2half_rn(acc[2][i][3] + gb1);
    }
}

// ===========================================================================
// FLASH attention: S = QK^T -> online softmax -> O = P V, fused.
// CTA: 64 q-rows x one batch. 256 threads / 8 warps. Key blocks of 64 (49 exact).
// S phase: warp = 16q x 32keys (k-half split w>>2); stats merged via SMEM.
// PV phase: 8 warps 2m x 4n, warp = 32q x 64ic.
// Dynamic SMEM 186112 B.
// ===========================================================================
constexpr int QT  = 64;
constexpr int KBK = 64;
constexpr int NKB = N_ / KBK;      // 49
constexpr int QKS = 264;           // halves per Q/K row (256 + 8 pad) = 528 B
constexpr int VPS = 72;            // halves per V/P row (64 + 8 pad)  = 144 B
// smem byte offsets
constexpr int SM_Q  = 0;                         // 64*528   = 33792
constexpr int SM_K  = 33792;                     // 2*64*528 = 67584
constexpr int SM_V  = 101376;                    // 2*256*144= 73728
constexpr int SM_P  = 175104;                    // 64*144   = 9216
constexpr int SM_PM = 184320;                    // 2*64 f   = 512
constexpr int SM_PS = 184832;                    // 2*64 f   = 512
constexpr int SM_M  = 185344;                    // 64 f
constexpr int SM_L  = 185600;                    // 64 f
constexpr int SM_SC = 185856;                    // 64 f
constexpr int SM_TOTAL = 186112;

__global__ __launch_bounds__(256) void flash_attn(
    const __half* __restrict__ Qg, const __half* __restrict__ Kg,
    const __half* __restrict__ Vtg, __half* __restrict__ Yg)
{
    extern __shared__ char smem[];
    __half* Qs = (__half*)(smem + SM_Q);
    __half* Ks = (__half*)(smem + SM_K);
    __half* Vs = (__half*)(smem + SM_V);
    __half* Ps = (__half*)(smem + SM_P);
    float* pmx = (float*)(smem + SM_PM);
    float* psm = (float*)(smem + SM_PS);
    float* m_s = (float*)(smem + SM_M);
    float* l_s = (float*)(smem + SM_L);
    float* sc  = (float*)(smem + SM_SC);

    const int b  = blockIdx.y;
    const int q0 = blockIdx.x * QT;
    const __half* Qb = Qg  + ((long long)b * NP_ + q0) * IC_;
    const __half* Kb = Kg  + (long long)b * NP_ * IC_;
    const __half* Vb = Vtg + (long long)b * IC_ * NP_;
    __half* Yb       = Yg  + ((long long)b * NP_ + q0) * IC_;

    const int tid = threadIdx.x;
    const int w = tid >> 5, lane = tid & 31;
    const int gid = lane >> 2, tig = lane & 3;

    if (tid < QT) { m_s[tid] = -1e30f; l_s[tid] = 0.f; }

    const int a_row = (lane & 7) + ((lane >> 3) & 1) * 8;
    const int a_kb  = (lane >> 4) * 16;
    const int b_row = (lane & 7) + (lane >> 4) * 8;
    const int b_kb  = ((lane >> 3) & 1) * 16;

    // S-phase mapping
    const int band = (w & 3) * 16;     // q band
    const int kh   = (w >> 2);         // key half (0/1)
    // PV-phase mapping
    const int wm = (w & 1) * 32;
    const int wn = (w >> 1) * 64;

    auto loadQ = [&]() {
        #pragma unroll
        for (int it = 0; it < 8; it++) {
            int lin = tid + it * 256;
            int row = lin >> 5, c = lin & 31;          // 64 rows x 32 chunks
            cp_async16(smem_u32(Qs + row * QKS + c * 8),
                       Qb + (long long)row * IC_ + c * 8);
        }
    };
    auto loadK = [&](int j, int bf) {
        const __half* src = Kb + (long long)j * KBK * IC_;
        __half* dst = Ks + bf * (64 * QKS);
        #pragma unroll
        for (int it = 0; it < 8; it++) {
            int lin = tid + it * 256;
            int row = lin >> 5, c = lin & 31;
            cp_async16(smem_u32(dst + row * QKS + c * 8),
                       src + (long long)row * IC_ + c * 8);
        }
    };
    auto loadV = [&](int j, int bf) {
        __half* dst = Vs + bf * (256 * VPS);
        #pragma unroll
        for (int it = 0; it < 8; it++) {
            int lin = tid + it * 256;
            int row = lin >> 3, c = lin & 7;           // 256 ic-rows x 8 chunks
            cp_async16(smem_u32(dst + row * VPS + c * 8),
                       Vb + (long long)row * NP_ + j * KBK + c * 8);
        }
    };

    float o[2][8][4];
    #pragma unroll
    for (int i = 0; i < 2; i++)
        #pragma unroll
        for (int jt = 0; jt < 8; jt++)
            #pragma unroll
            for (int r = 0; r < 4; r++) o[i][jt][r] = 0.0f;

    loadQ(); loadK(0, 0); loadV(0, 0); cp_commit(); cp_wait0(); __syncthreads();

    int buf = 0;
    const uint32_t qbase = smem_u32(Qs);
    const uint32_t pbase = smem_u32(Ps);

    for (int j = 0; j < NKB; j++) {
        const bool nxt = (j + 1 < NKB);
        if (nxt) { loadK(j + 1, buf ^ 1); loadV(j + 1, buf ^ 1); cp_commit(); }

        // ---- S = Q K^T : this warp 16q x 32keys
        const uint32_t kbase = smem_u32(Ks + buf * (64 * QKS));
        float s[4][4];
        #pragma unroll
        for (int jt = 0; jt < 4; jt++)
            #pragma unroll
            for (int r = 0; r < 4; r++) s[jt][r] = 0.0f;

        #pragma unroll
        for (int kst = 0; kst < 16; kst++) {
            uint32_t af[4];
            ldsm_x4(af[0], af[1], af[2], af[3],
                    qbase + (band + a_row) * (QKS * 2) + kst * 32 + a_kb);
            uint32_t bfr[4][2];
            #pragma unroll
            for (int jj = 0; jj < 2; jj++)
                ldsm_x4(bfr[jj * 2][0], bfr[jj * 2][1], bfr[jj * 2 + 1][0], bfr[jj * 2 + 1][1],
                        kbase + (kh * 32 + jj * 16 + b_row) * (QKS * 2) + kst * 32 + b_kb);
            #pragma unroll
            for (int jt = 0; jt < 4; jt++)
                mma_f16(s[jt][0], s[jt][1], s[jt][2], s[jt][3],
                        af[0], af[1], af[2], af[3], bfr[jt][0], bfr[jt][1]);
        }

        // ---- partial row max over this warp's 32 keys
        const int r0 = band + gid, r1 = band + gid + 8;
        float pm0 = -1e30f, pm1 = -1e30f;
        #pragma unroll
        for (int jt = 0; jt < 4; jt++) {
            pm0 = fmaxf(pm0, fmaxf(s[jt][0], s[jt][1]));
            pm1 = fmaxf(pm1, fmaxf(s[jt][2], s[jt][3]));
        }
        pm0 = fmaxf(pm0, __shfl_xor_sync(~0u, pm0, 1));
        pm0 = fmaxf(pm0, __shfl_xor_sync(~0u, pm0, 2));
        pm1 = fmaxf(pm1, __shfl_xor_sync(~0u, pm1, 1));
        pm1 = fmaxf(pm1, __shfl_xor_sync(~0u, pm1, 2));
        if (tig == 0) { pmx[kh * 64 + r0] = pm0; pmx[kh * 64 + r1] = pm1; }
        __syncthreads();                                     // A

        const float mo0 = m_s[r0], mo1 = m_s[r1];
        const float mn0 = fmaxf(mo0, fmaxf(pmx[r0], pmx[64 + r0]));
        const float mn1 = fmaxf(mo1, fmaxf(pmx[r1], pmx[64 + r1]));

        float sum0 = 0.f, sum1 = 0.f;
        #pragma unroll
        for (int jt = 0; jt < 4; jt++) {
            float p00 = __expf(s[jt][0] - mn0), p01 = __expf(s[jt][1] - mn0);
            float p10 = __expf(s[jt][2] - mn1), p11 = __expf(s[jt][3] - mn1);
            sum0 += p00 + p01;  sum1 += p10 + p11;
            int key = kh * 32 + jt * 8 + tig * 2;
            *(__half2*)(Ps + r0 * VPS + key) = __floats2half2_rn(p00, p01);
            *(__half2*)(Ps + r1 * VPS + key) = __floats2half2_rn(p10, p11);
        }
        sum0 += __shfl_xor_sync(~0u, sum0, 1);
        sum0 += __shfl_xor_sync(~0u, sum0, 2);
        sum1 += __shfl_xor_sync(~0u, sum1, 1);
        sum1 += __shfl_xor_sync(~0u, sum1, 2);
        if (tig == 0) { psm[kh * 64 + r0] = sum0; psm[kh * 64 + r1] = sum1; }
        __syncthreads();                                     // B

        if (kh == 0 && tig == 0) {
            float sc0 = __expf(mo0 - mn0);
            float sc1 = __expf(mo1 - mn1);
            l_s[r0] = l_s[r0] * sc0 + psm[r0] + psm[64 + r0];
            l_s[r1] = l_s[r1] * sc1 + psm[r1] + psm[64 + r1];
            m_s[r0] = mn0;  m_s[r1] = mn1;
            sc[r0] = sc0;   sc[r1] = sc1;
        }
        __syncthreads();                                     // C

        // ---- PV: rescale O then accumulate P @ V
        #pragma unroll
        for (int i = 0; i < 2; i++) {
            float f0 = sc[wm + i * 16 + gid];
            float f1 = sc[wm + i * 16 + gid + 8];
            #pragma unroll
            for (int jt = 0; jt < 8; jt++) {
                o[i][jt][0] *= f0;  o[i][jt][1] *= f0;
                o[i][jt][2] *= f1;  o[i][jt][3] *= f1;
            }
        }
        const uint32_t vbase = smem_u32(Vs + buf * (256 * VPS));
        #pragma unroll
        for (int kst = 0; kst < 4; kst++) {
            uint32_t af[2][4];
            #pragma unroll
            for (int i = 0; i < 2; i++)
                ldsm_x4(af[i][0], af[i][1], af[i][2], af[i][3],
                        pbase + (wm + i * 16 + a_row) * (VPS * 2) + kst * 32 + a_kb);
            uint32_t bfr[8][2];
            #pragma unroll
            for (int jj = 0; jj < 4; jj++)
                ldsm_x4(bfr[jj * 2][0], bfr[jj * 2][1], bfr[jj * 2 + 1][0], bfr[jj * 2 + 1][1],
                        vbase + (wn + jj * 16 + b_row) * (VPS * 2) + kst * 32 + b_kb);
            #pragma unroll
            for (int i = 0; i < 2; i++)
                #pragma unroll
                for (int jt = 0; jt < 8; jt++)
                    mma_f16(o[i][jt][0], o[i][jt][1], o[i][jt][2], o[i][jt][3],
                            af[i][0], af[i][1], af[i][2], af[i][3],
                            bfr[jt][0], bfr[jt][1]);
        }

        if (nxt) { cp_wait0(); __syncthreads(); buf ^= 1; }
    }

    // ---- epilogue: normalize by l and store fp16
    #pragma unroll
    for (int i = 0; i < 2; i++) {
        int r0 = wm + i * 16 + gid;
        float inv0 = 1.0f / l_s[r0];
        float inv1 = 1.0f / l_s[r0 + 8];
        #pragma unroll
        for (int jt = 0; jt < 8; jt++) {
            int col = wn + jt * 8 + tig * 2;
            *(__half2*)(Yb + (long long)r0 * IC_ + col) =
                __floats2half2_rn(o[i][jt][0] * inv0, o[i][jt][1] * inv0);
            *(__half2*)(Yb + (long long)(r0 + 8) * IC_ + col) =
                __floats2half2_rn(o[i][jt][2] * inv1, o[i][jt][3] * inv1);
        }
    }
}

// ===========================================================================
// y2 = y1h * wzh^T + bias, fp16 mma + ldmatrix, 64x64x32 with fused BN stats
// ===========================================================================
__global__ __launch_bounds__(128) void y2h_stats(
    const __half* __restrict__ A, const float* __restrict__ bias,
    float* __restrict__ Cc)
{
    const long long z = blockIdx.z;
    A  += z * (long long)NP_ * IC_;
    Cc += z * (long long)N_ * C_;

    const int m0 = blockIdx.x * 64;
    const int n0 = blockIdx.y * 64;
    const int tid = threadIdx.x;
    const int w = tid >> 5, lane = tid & 31;
    const int gid = lane >> 2, tig = lane & 3;
    const int wm = (w & 1) * 32, wn = (w >> 1) * 32;

    __shared__ uint32_t As[64 * FSTR];
    __shared__ uint32_t Bs[64 * FSTR];
    __shared__ float csum[64];
    __shared__ float csq [64];

    if (tid < 64) { csum[tid] = 0.f; csq[tid] = 0.f; }

    const int a_row = (lane & 7) + ((lane >> 3) & 1) * 8;
    const int a_kb  = (lane >> 4) * 16;
    const int b_row = (lane & 7) + (lane >> 4) * 8;
    const int b_kb  = ((lane >> 3) & 1) * 16;

    float acc[2][4][4];
    #pragma unroll
    for (int i = 0; i < 2; i++)
        #pragma unroll
        for (int j = 0; j < 4; j++)
            #pragma unroll
            for (int r = 0; r < 4; r++) acc[i][j][r] = 0.0f;

    for (int k0 = 0; k0 < IC_; k0 += 32) {
        #pragma unroll
        for (int it = 0; it < 2; it++) {
            int lin = tid + it * 128;
            int row = lin >> 2, k8 = (lin & 3) << 3, kw = (lin & 3) << 2;
            *(uint4*)(&As[row * FSTR + kw]) =
                *(const uint4*)(A + (long long)(m0 + row) * IC_ + k0 + k8);
            *(uint4*)(&Bs[row * FSTR + kw]) =
                *(const uint4*)(g_wzh + (long long)(n0 + row) * IC_ + k0 + k8);
        }
        __syncthreads();

        const uint32_t abase = smem_u32(As);
        const uint32_t bbase = smem_u32(Bs);
        #pragma unroll
        for (int ks = 0; ks < 2; ks++) {
            const int kb = ks * 32;
            uint32_t af[2][4];
            #pragma unroll
            for (int i = 0; i < 2; i++)
                ldsm_x4(af[i][0], af[i][1], af[i][2], af[i][3],
                        abase + (wm + i * 16 + a_row) * FSTRB + kb + a_kb);
            uint32_t bf[4][2];
            #pragma unroll
            for (int jj = 0; jj < 2; jj++)
                ldsm_x4(bf[jj * 2][0], bf[jj * 2][1], bf[jj * 2 + 1][0], bf[jj * 2 + 1][1],
                        bbase + (wn + jj * 16 + b_row) * FSTRB + kb + b_kb);
            #pragma unroll
            for (int i = 0; i < 2; i++)
                #pragma unroll
                for (int j = 0; j < 4; j++)
                    mma_f16(acc[i][j][0], acc[i][j][1], acc[i][j][2], acc[i][j][3],
                            af[i][0], af[i][1], af[i][2], af[i][3],
                            bf[j][0], bf[j][1]);
        }
        __syncthreads();
    }

    #pragma unroll
    for (int j = 0; j < 4; j++) {
        int lcol = wn + j * 8 + tig * 2;
        int gcol = n0 + lcol;
        float b0v = bias[gcol], b1v = bias[gcol + 1];
        float s0 = 0.f, q0 = 0.f, s1 = 0.f, q1 = 0.f;
        #pragma unroll
        for (int i = 0; i < 2; i++) {
            int grow = m0 + wm + i * 16 + gid;
            float v00 = acc[i][j][0] + b0v;
            float v01 = acc[i][j][1] + b1v;
            float v10 = acc[i][j][2] + b0v;
            float v11 = acc[i][j][3] + b1v;
            *(float2*)(Cc + (long long)grow * C_ + gcol)       = make_float2(v00, v01);
            *(float2*)(Cc + (long long)(grow + 8) * C_ + gcol) = make_float2(v10, v11);
            s0 += v00 + v10;  q0 += v00 * v00 + v10 * v10;
            s1 += v01 + v11;  q1 += v01 * v01 + v11 * v11;
        }
        atomicAdd(&csum[lcol],     s0);
        atomicAdd(&csq [lcol],     q0);
        atomicAdd(&csum[lcol + 1], s1);
        atomicAdd(&csq [lcol + 1], q1);
    }
    __syncthreads();
    if (tid < 64) {
        atomicAdd(&g_sum  [n0 + tid], (double)csum[tid]);
        atomicAdd(&g_sumsq[n0 + tid], (double)csq [tid]);
    }
}

// ---------------------------------------------------------------------------
// BN: zero stats + final (unchanged)
// ---------------------------------------------------------------------------
__global__ void zero_stats()
{
    int t = threadIdx.x;
    g_sum[t] = 0.0;
    g_sumsq[t] = 0.0;
}

__global__ __launch_bounds__(256) void bn_final(
    const float* __restrict__ x,
    const float* __restrict__ bn_w, const float* __restrict__ bn_b,
    float* __restrict__ out)
{
    __shared__ float t[32][33];
    const int b  = blockIdx.z;
    const int c0 = blockIdx.y * 32;
    const int n0 = blockIdx.x * 32;
    const int tx = threadIdx.x, ty = threadIdx.y;

    #pragma unroll
    for (int j = 0; j < 32; j += 8) {
        int n = n0 + ty + j;
        t[ty + j][tx] = g_y2[((size_t)(b * N_ + n)) * C_ + c0 + tx];
    }
    __syncthreads();

    const double cnt = (double)ROWS_TOTAL;
    #pragma unroll
    for (int j = 0; j < 32; j += 8) {
        int c = c0 + ty + j;
        double mean = g_sum[c] / cnt;
        double var  = g_sumsq[c] / cnt - mean * mean;
        float inv = (float)rsqrt(var + 1e-5);
        float w = bn_w[c], bb = bn_b[c];
        int n = n0 + tx;
        size_t oidx = ((size_t)b * C_ + c) * (size_t)N_ + n;
        float v = t[tx][ty + j];
        out[oidx] = (v - (float)mean) * inv * w + bb + x[oidx];
    }
}

// ---------------------------------------------------------------------------
// Launch
// ---------------------------------------------------------------------------
extern "C" void kernel_launch(void* const* d_in, const int* in_sizes, int n_in,
                              void* d_out, int out_size)
{
    const float* x       = (const float*)d_in[0];
    const float* theta_w = (const float*)d_in[1];
    const float* theta_b = (const float*)d_in[2];
    const float* phi_w   = (const float*)d_in[3];
    const float* phi_b   = (const float*)d_in[4];
    const float* gw      = (const float*)d_in[5];
    const float* gb      = (const float*)d_in[6];
    const float* wz_w    = (const float*)d_in[7];
    const float* wz_b    = (const float*)d_in[8];
    const float* bn_w    = (const float*)d_in[9];
    const float* bn_b    = (const float*)d_in[10];
    float* out = (float*)d_out;

    float *y2;
    __half *Qh, *Kh, *Vt, *y1h;
    cudaGetSymbolAddress((void**)&Qh,  g_Qh);
    cudaGetSymbolAddress((void**)&Kh,  g_Kh);
    cudaGetSymbolAddress((void**)&Vt,  g_Vt);
    cudaGetSymbolAddress((void**)&y1h, g_y1h);
    cudaGetSymbolAddress((void**)&y2,  g_y2);

    cudaFuncSetAttribute(flash_attn,
                         cudaFuncAttributeMaxDynamicSharedMemorySize, SM_TOTAL);

    zero_stats<<<1, 512>>>();

    conv_weights<<<(4 * IC_ * C_) / 256, 256>>>(theta_w, phi_w, gw, wz_w);
    x_to_h<<<dim3(N_ / 32, C_ / 32, B_), dim3(32, 8)>>>(x);

    qkv3_f16<<<dim3(N_ / 64, IC_ / 64, B_), 256>>>(
        theta_b, phi_b, gb, Qh, Kh, Vt);

    // fused attention: S + softmax + PV
    flash_attn<<<dim3(NP_ / QT, B_), 256, SM_TOTAL>>>(Qh, Kh, Vt, y1h);

    y2h_stats<<<dim3(N_ / 64, C_ / 64, B_), 128>>>(y1h, wz_b, y2);

    bn_final<<<dim3(N_ / 32, C_ / 32, B_), dim3(32, 8)>>>(x, bn_w, bn_b, out);
}

// round 16
// speedup vs baseline: 1.2464x; 1.0662x over previous
#include <cuda_runtime.h>
#include <cuda_fp16.h>
#include <math.h>
#include <stdint.h>

// Problem constants
#define B_   8
#define C_   512
#define N_   3136   // 56*56
#define NP_  3200   // N padded to multiple of 128
#define IC_  256
#define ROWS_TOTAL (B_ * N_)   // 25088

// ---------------------------------------------------------------------------
// Scratch
// ---------------------------------------------------------------------------
__device__ __half g_xh [(size_t)B_ * NP_ * C_];   // x fp16 transposed [token][c]
__device__ __half g_Wh [(size_t)3 * IC_ * C_];    // theta/phi/g weights fp16
__device__ __half g_wzh[(size_t)C_ * IC_];        // wz fp16
__device__ __half g_Qh [(size_t)B_ * NP_ * IC_];  // Q fp16 [token][i]
__device__ __half g_Kh [(size_t)B_ * NP_ * IC_];  // K fp16 [token][i]
__device__ __half g_Vt [(size_t)B_ * IC_ * NP_];  // V fp16 transposed [i][token]
__device__ __half g_y1h[(size_t)B_ * NP_ * IC_];  // attention out fp16
__device__ float  g_y2 [(size_t)B_ * N_ * C_];
__device__ double g_sum[C_];
__device__ double g_sumsq[C_];

// ---------------------------------------------------------------------------
// mma / ldmatrix / cp.async helpers
// ---------------------------------------------------------------------------
__device__ __forceinline__ void mma_f16(float& d0, float& d1, float& d2, float& d3,
                                        uint32_t a0, uint32_t a1, uint32_t a2, uint32_t a3,
                                        uint32_t b0, uint32_t b1) {
    asm volatile(
        "mma.sync.aligned.m16n8k16.row.col.f32.f16.f16.f32 "
        "{%0,%1,%2,%3}, {%4,%5,%6,%7}, {%8,%9}, {%0,%1,%2,%3};\n"
        : "+f"(d0), "+f"(d1), "+f"(d2), "+f"(d3)
        : "r"(a0), "r"(a1), "r"(a2), "r"(a3), "r"(b0), "r"(b1));
}
__device__ __forceinline__ void ldsm_x4(uint32_t& r0, uint32_t& r1, uint32_t& r2, uint32_t& r3,
                                        uint32_t addr) {
    asm volatile("ldmatrix.sync.aligned.m8n8.x4.shared.b16 {%0,%1,%2,%3}, [%4];"
                 : "=r"(r0), "=r"(r1), "=r"(r2), "=r"(r3) : "r"(addr));
}
__device__ __forceinline__ void ldsm_x2(uint32_t& r0, uint32_t& r1, uint32_t addr) {
    asm volatile("ldmatrix.sync.aligned.m8n8.x2.shared.b16 {%0,%1}, [%2];"
                 : "=r"(r0), "=r"(r1) : "r"(addr));
}
__device__ __forceinline__ uint32_t smem_u32(const void* p) {
    return (uint32_t)__cvta_generic_to_shared(p);
}
__device__ __forceinline__ void cp_async16(uint32_t saddr, const void* gptr) {
    asm volatile("cp.async.cg.shared.global [%0], [%1], 16;" :: "r"(saddr), "l"(gptr));
}
__device__ __forceinline__ void cp_commit() {
    asm volatile("cp.async.commit_group;");
}
__device__ __forceinline__ void cp_wait0() {
    asm volatile("cp.async.wait_group 0;");
}

constexpr int FSTR = 20;       // 20 words = 80 bytes per SMEM row (32 data halves + pad)
constexpr int FSTRB = 80;      // bytes

// ---------------------------------------------------------------------------
// Prep kernels
// ---------------------------------------------------------------------------
__global__ void conv_weights(const float* __restrict__ tw, const float* __restrict__ pw,
                             const float* __restrict__ gw, const float* __restrict__ wz)
{
    const int WSZ = IC_ * C_;            // 131072
    int idx = blockIdx.x * 256 + threadIdx.x;
    if (idx < 3 * WSZ) {
        const float* src = (idx < WSZ) ? tw : (idx < 2 * WSZ ? pw : gw);
        g_Wh[idx] = __float2half_rn(src[idx % WSZ]);
    } else {
        int off = idx - 3 * WSZ;
        g_wzh[off] = __float2half_rn(wz[off]);
    }
}

__global__ __launch_bounds__(256) void x_to_h(const float* __restrict__ x)
{
    __shared__ float t[32][33];
    const int b  = blockIdx.z;
    const int n0 = blockIdx.x * 32;
    const int c0 = blockIdx.y * 32;
    const float* xb = x + (size_t)b * C_ * N_;
    __half* xh = g_xh + (size_t)b * NP_ * C_;
    const int tx = threadIdx.x, ty = threadIdx.y;

    #pragma unroll
    for (int j = 0; j < 32; j += 8)
        t[ty + j][tx] = xb[(size_t)(c0 + ty + j) * N_ + n0 + tx];
    __syncthreads();
    #pragma unroll
    for (int j = 0; j < 32; j += 8)
        xh[(size_t)(n0 + ty + j) * C_ + c0 + tx] = __float2half_rn(t[tx][ty + j]);
}

// ===========================================================================
// Fused QKV (unchanged R14: cp.async + ldmatrix, 64x64x32)
// ===========================================================================
__global__ __launch_bounds__(256) void qkv3_f16(
    const float* __restrict__ tb, const float* __restrict__ pb,
    const float* __restrict__ gb,
    __half* __restrict__ Q, __half* __restrict__ K, __half* __restrict__ Vt)
{
    const long long z = blockIdx.z;
    const __half* xh = g_xh + z * (long long)NP_ * C_;
    Q  += z * (long long)NP_ * IC_;
    K  += z * (long long)NP_ * IC_;
    Vt += z * (long long)IC_ * NP_;

    const int m0 = blockIdx.x * 64;
    const int n0 = blockIdx.y * 64;
    const int tid = threadIdx.x;
    const int w = tid >> 5, lane = tid & 31;
    const int gid = lane >> 2, tig = lane & 3;
    const int wn = w * 8;

    __shared__ uint32_t Ah[2][64 * FSTR];
    __shared__ uint32_t Bh[2][192 * FSTR];

    const int a_row = (lane & 7) + ((lane >> 3) & 1) * 8;
    const int a_kb  = (lane >> 4) * 16;
    const int b_row = (lane & 7);
    const int b_kb  = (((lane & 15) >> 3) & 1) * 16;

    float acc[3][4][4];
    #pragma unroll
    for (int s = 0; s < 3; s++)
        #pragma unroll
        for (int i = 0; i < 4; i++)
            #pragma unroll
            for (int r = 0; r < 4; r++) acc[s][i][r] = 0.0f;

    auto aload = [&](int k0, int b) {
        {
            int row = tid >> 2, k8 = (tid & 3) << 3, kw = (tid & 3) << 2;
            cp_async16(smem_u32(&Ah[b][row * FSTR + kw]),
                       xh + (long long)(m0 + row) * C_ + k0 + k8);
        }
        #pragma unroll
        for (int it = 0; it < 3; it++) {
            int lin = tid + it * 256;
            int brow = lin >> 2, k8 = (lin & 3) << 3, kw = (lin & 3) << 2;
            int s = brow >> 6, wr = brow & 63;
            cp_async16(smem_u32(&Bh[b][brow * FSTR + kw]),
                       g_Wh + ((long long)s * IC_ + n0 + wr) * C_ + k0 + k8);
        }
    };

    aload(0, 0); cp_commit(); cp_wait0(); __syncthreads();
    int buf = 0;
    for (int k0 = 0; k0 < C_; k0 += 32) {
        const bool nxt = (k0 + 32 < C_);
        if (nxt) { aload(k0 + 32, buf ^ 1); cp_commit(); }

        const uint32_t abase = smem_u32(Ah[buf]);
        const uint32_t bbase = smem_u32(Bh[buf]);
        #pragma unroll
        for (int ks = 0; ks < 2; ks++) {
            const int kb = ks * 32;
            uint32_t af[4][4];
            #pragma unroll
            for (int i = 0; i < 4; i++)
                ldsm_x4(af[i][0], af[i][1], af[i][2], af[i][3],
                        abase + (i * 16 + a_row) * FSTRB + kb + a_kb);
            #pragma unroll
            for (int s = 0; s < 3; s++) {
                uint32_t b0, b1;
                ldsm_x2(b0, b1,
                        bbase + (s * 64 + wn + b_row) * FSTRB + kb + b_kb);
                #pragma unroll
                for (int i = 0; i < 4; i++)
                    mma_f16(acc[s][i][0], acc[s][i][1], acc[s][i][2], acc[s][i][3],
                            af[i][0], af[i][1], af[i][2], af[i][3], b0, b1);
            }
        }
        if (nxt) { cp_wait0(); __syncthreads(); buf ^= 1; }
    }

    const int gcol = n0 + wn + tig * 2;
    const float tb0 = tb[gcol], tb1 = tb[gcol + 1];
    const float pb0 = pb[gcol], pb1 = pb[gcol + 1];
    const float gb0 = gb[gcol], gb1 = gb[gcol + 1];
    #pragma unroll
    for (int i = 0; i < 4; i++) {
        int grow = m0 + i * 16 + gid;
        *(__half2*)(Q + (long long)grow * IC_ + gcol) =
            __floats2half2_rn(acc[0][i][0] + tb0, acc[0][i][1] + tb1);
        *(__half2*)(Q + (long long)(grow + 8) * IC_ + gcol) =
            __floats2half2_rn(acc[0][i][2] + tb0, acc[0][i][3] + tb1);
        *(__half2*)(K + (long long)grow * IC_ + gcol) =
            __floats2half2_rn(acc[1][i][0] + pb0, acc[1][i][1] + pb1);
        *(__half2*)(K + (long long)(grow + 8) * IC_ + gcol) =
            __floats2half2_rn(acc[1][i][2] + pb0, acc[1][i][3] + pb1);
        Vt[(long long)gcol       * NP_ + grow]     = __float2half_rn(acc[2][i][0] + gb0);
        Vt[(long long)(gcol + 1) * NP_ + grow]     = __float2half_rn(acc[2][i][1] + gb1);
        Vt[(long long)gcol       * NP_ + grow + 8] = __float2half_rn(acc[2][i][2] + gb0);
        Vt[(long long)(gcol + 1) * NP_ + grow + 8] = __float2half_rn(acc[2][i][3] + gb1);
    }
}

// ===========================================================================
// FLASH attention v2: Q fragments hoisted to registers (1 CTA/SM -> regs free),
// 3 barriers/iter (sc written pre-B; m/l updates post-B).
// CTA: 64 q-rows x one batch, 256 threads / 8 warps, key blocks of 64.
// ===========================================================================
constexpr int QT  = 64;
constexpr int KBK = 64;
constexpr int NKB = N_ / KBK;      // 49
constexpr int QKS = 264;           // halves per Q/K row (256 + 8 pad) = 528 B
constexpr int VPS = 72;            // halves per V/P row (64 + 8 pad)  = 144 B
constexpr int SM_Q  = 0;                         // 64*528   = 33792
constexpr int SM_K  = 33792;                     // 2*64*528 = 67584
constexpr int SM_V  = 101376;                    // 2*256*144= 73728
constexpr int SM_P  = 175104;                    // 64*144   = 9216
constexpr int SM_PM = 184320;                    // 2*64 f   = 512
constexpr int SM_PS = 184832;                    // 2*64 f   = 512
constexpr int SM_M  = 185344;                    // 64 f
constexpr int SM_L  = 185600;                    // 64 f
constexpr int SM_SC = 185856;                    // 64 f
constexpr int SM_TOTAL = 186112;

__global__ __launch_bounds__(256, 1) void flash_attn(
    const __half* __restrict__ Qg, const __half* __restrict__ Kg,
    const __half* __restrict__ Vtg, __half* __restrict__ Yg)
{
    extern __shared__ char smem[];
    __half* Qs = (__half*)(smem + SM_Q);
    __half* Ks = (__half*)(smem + SM_K);
    __half* Vs = (__half*)(smem + SM_V);
    __half* Ps = (__half*)(smem + SM_P);
    float* pmx = (float*)(smem + SM_PM);
    float* psm = (float*)(smem + SM_PS);
    float* m_s = (float*)(smem + SM_M);
    float* l_s = (float*)(smem + SM_L);
    float* sc  = (float*)(smem + SM_SC);

    const int b  = blockIdx.y;
    const int q0 = blockIdx.x * QT;
    const __half* Qb = Qg  + ((long long)b * NP_ + q0) * IC_;
    const __half* Kb = Kg  + (long long)b * NP_ * IC_;
    const __half* Vb = Vtg + (long long)b * IC_ * NP_;
    __half* Yb       = Yg  + ((long long)b * NP_ + q0) * IC_;

    const int tid = threadIdx.x;
    const int w = tid >> 5, lane = tid & 31;
    const int gid = lane >> 2, tig = lane & 3;

    if (tid < QT) { m_s[tid] = -1e30f; l_s[tid] = 0.f; }

    const int a_row = (lane & 7) + ((lane >> 3) & 1) * 8;
    const int a_kb  = (lane >> 4) * 16;
    const int b_row = (lane & 7) + (lane >> 4) * 8;
    const int b_kb  = ((lane >> 3) & 1) * 16;

    const int band = (w & 3) * 16;     // S-phase q band
    const int kh   = (w >> 2);         // S-phase key half
    const int wm = (w & 1) * 32;       // PV q offset
    const int wn = (w >> 1) * 64;      // PV ic offset

    auto loadQ = [&]() {
        #pragma unroll
        for (int it = 0; it < 8; it++) {
            int lin = tid + it * 256;
            int row = lin >> 5, c = lin & 31;
            cp_async16(smem_u32(Qs + row * QKS + c * 8),
                       Qb + (long long)row * IC_ + c * 8);
        }
    };
    auto loadK = [&](int j, int bf) {
        const __half* src = Kb + (long long)j * KBK * IC_;
        __half* dst = Ks + bf * (64 * QKS);
        #pragma unroll
        for (int it = 0; it < 8; it++) {
            int lin = tid + it * 256;
            int row = lin >> 5, c = lin & 31;
            cp_async16(smem_u32(dst + row * QKS + c * 8),
                       src + (long long)row * IC_ + c * 8);
        }
    };
    auto loadV = [&](int j, int bf) {
        __half* dst = Vs + bf * (256 * VPS);
        #pragma unroll
        for (int it = 0; it < 8; it++) {
            int lin = tid + it * 256;
            int row = lin >> 3, c = lin & 7;
            cp_async16(smem_u32(dst + row * VPS + c * 8),
                       Vb + (long long)row * NP_ + j * KBK + c * 8);
        }
    };

    float o[2][8][4];
    #pragma unroll
    for (int i = 0; i < 2; i++)
        #pragma unroll
        for (int jt = 0; jt < 8; jt++)
            #pragma unroll
            for (int r = 0; r < 4; r++) o[i][jt][r] = 0.0f;

    loadQ(); loadK(0, 0); loadV(0, 0); cp_commit(); cp_wait0(); __syncthreads();

    // ---- hoist this warp's Q fragments into registers (64 regs; 1 CTA/SM)
    const uint32_t qbase = smem_u32(Qs);
    uint32_t qf[16][4];
    #pragma unroll
    for (int kst = 0; kst < 16; kst++)
        ldsm_x4(qf[kst][0], qf[kst][1], qf[kst][2], qf[kst][3],
                qbase + (band + a_row) * (QKS * 2) + kst * 32 + a_kb);

    int buf = 0;
    const uint32_t pbase = smem_u32(Ps);

    for (int j = 0; j < NKB; j++) {
        const bool nxt = (j + 1 < NKB);
        if (nxt) { loadK(j + 1, buf ^ 1); loadV(j + 1, buf ^ 1); cp_commit(); }

        // ---- S = Q K^T : this warp 16q x 32keys (K fragments only from SMEM)
        const uint32_t kbase = smem_u32(Ks + buf * (64 * QKS));
        float s[4][4];
        #pragma unroll
        for (int jt = 0; jt < 4; jt++)
            #pragma unroll
            for (int r = 0; r < 4; r++) s[jt][r] = 0.0f;

        #pragma unroll
        for (int kst = 0; kst < 16; kst++) {
            uint32_t bfr[4][2];
            #pragma unroll
            for (int jj = 0; jj < 2; jj++)
                ldsm_x4(bfr[jj * 2][0], bfr[jj * 2][1], bfr[jj * 2 + 1][0], bfr[jj * 2 + 1][1],
                        kbase + (kh * 32 + jj * 16 + b_row) * (QKS * 2) + kst * 32 + b_kb);
            #pragma unroll
            for (int jt = 0; jt < 4; jt++)
                mma_f16(s[jt][0], s[jt][1], s[jt][2], s[jt][3],
                        qf[kst][0], qf[kst][1], qf[kst][2], qf[kst][3],
                        bfr[jt][0], bfr[jt][1]);
        }

        // ---- partial row max over this warp's 32 keys
        const int r0 = band + gid, r1 = band + gid + 8;
        float pm0 = -1e30f, pm1 = -1e30f;
        #pragma unroll
        for (int jt = 0; jt < 4; jt++) {
            pm0 = fmaxf(pm0, fmaxf(s[jt][0], s[jt][1]));
            pm1 = fmaxf(pm1, fmaxf(s[jt][2], s[jt][3]));
        }
        pm0 = fmaxf(pm0, __shfl_xor_sync(~0u, pm0, 1));
        pm0 = fmaxf(pm0, __shfl_xor_sync(~0u, pm0, 2));
        pm1 = fmaxf(pm1, __shfl_xor_sync(~0u, pm1, 1));
        pm1 = fmaxf(pm1, __shfl_xor_sync(~0u, pm1, 2));
        if (tig == 0) { pmx[kh * 64 + r0] = pm0; pmx[kh * 64 + r1] = pm1; }
        __syncthreads();                                     // A

        const float mo0 = m_s[r0], mo1 = m_s[r1];
        const float mn0 = fmaxf(mo0, fmaxf(pmx[r0], pmx[64 + r0]));
        const float mn1 = fmaxf(mo1, fmaxf(pmx[r1], pmx[64 + r1]));
        // sc written early so barrier B covers it (kh==0 copy only)
        if (kh == 0 && tig == 0) {
            sc[r0] = __expf(mo0 - mn0);
            sc[r1] = __expf(mo1 - mn1);
        }

        float sum0 = 0.f, sum1 = 0.f;
        #pragma unroll
        for (int jt = 0; jt < 4; jt++) {
            float p00 = __expf(s[jt][0] - mn0), p01 = __expf(s[jt][1] - mn0);
            float p10 = __expf(s[jt][2] - mn1), p11 = __expf(s[jt][3] - mn1);
            sum0 += p00 + p01;  sum1 += p10 + p11;
            int key = kh * 32 + jt * 8 + tig * 2;
            *(__half2*)(Ps + r0 * VPS + key) = __floats2half2_rn(p00, p01);
            *(__half2*)(Ps + r1 * VPS + key) = __floats2half2_rn(p10, p11);
        }
        sum0 += __shfl_xor_sync(~0u, sum0, 1);
        sum0 += __shfl_xor_sync(~0u, sum0, 2);
        sum1 += __shfl_xor_sync(~0u, sum1, 1);
        sum1 += __shfl_xor_sync(~0u, sum1, 2);
        if (tig == 0) { psm[kh * 64 + r0] = sum0; psm[kh * 64 + r1] = sum1; }
        __syncthreads();                                     // B

        // m/l updates post-B; next reads are behind the flip barrier (or final)
        if (kh == 0 && tig == 0) {
            l_s[r0] = l_s[r0] * sc[r0] + psm[r0] + psm[64 + r0];
            l_s[r1] = l_s[r1] * sc[r1] + psm[r1] + psm[64 + r1];
            m_s[r0] = mn0;  m_s[r1] = mn1;
        }

        // ---- PV: rescale O then accumulate P @ V
        #pragma unroll
        for (int i = 0; i < 2; i++) {
            float f0 = sc[wm + i * 16 + gid];
            float f1 = sc[wm + i * 16 + gid + 8];
            #pragma unroll
            for (int jt = 0; jt < 8; jt++) {
                o[i][jt][0] *= f0;  o[i][jt][1] *= f0;
                o[i][jt][2] *= f1;  o[i][jt][3] *= f1;
            }
        }
        const uint32_t vbase = smem_u32(Vs + buf * (256 * VPS));
        #pragma unroll
        for (int kst = 0; kst < 4; kst++) {
            uint32_t af[2][4];
            #pragma unroll
            for (int i = 0; i < 2; i++)
                ldsm_x4(af[i][0], af[i][1], af[i][2], af[i][3],
                        pbase + (wm + i * 16 + a_row) * (VPS * 2) + kst * 32 + a_kb);
            uint32_t bfr[8][2];
            #pragma unroll
            for (int jj = 0; jj < 4; jj++)
                ldsm_x4(bfr[jj * 2][0], bfr[jj * 2][1], bfr[jj * 2 + 1][0], bfr[jj * 2 + 1][1],
                        vbase + (wn + jj * 16 + b_row) * (VPS * 2) + kst * 32 + b_kb);
            #pragma unroll
            for (int i = 0; i < 2; i++)
                #pragma unroll
                for (int jt = 0; jt < 8; jt++)
                    mma_f16(o[i][jt][0], o[i][jt][1], o[i][jt][2], o[i][jt][3],
                            af[i][0], af[i][1], af[i][2], af[i][3],
                            bfr[jt][0], bfr[jt][1]);
        }

        if (nxt) { cp_wait0(); __syncthreads(); buf ^= 1; }
    }

    __syncthreads();   // l_s visibility for epilogue

    // ---- epilogue: normalize by l and store fp16
    #pragma unroll
    for (int i = 0; i < 2; i++) {
        int r0 = wm + i * 16 + gid;
        float inv0 = 1.0f / l_s[r0];
        float inv1 = 1.0f / l_s[r0 + 8];
        #pragma unroll
        for (int jt = 0; jt < 8; jt++) {
            int col = wn + jt * 8 + tig * 2;
            *(__half2*)(Yb + (long long)r0 * IC_ + col) =
                __floats2half2_rn(o[i][jt][0] * inv0, o[i][jt][1] * inv0);
            *(__half2*)(Yb + (long long)(r0 + 8) * IC_ + col) =
                __floats2half2_rn(o[i][jt][2] * inv1, o[i][jt][3] * inv1);
        }
    }
}

// ===========================================================================
// y2 = y1h * wzh^T + bias, fp16 mma + ldmatrix, 64x64x32 with fused BN stats
// ===========================================================================
__global__ __launch_bounds__(128) void y2h_stats(
    const __half* __restrict__ A, const float* __restrict__ bias,
    float* __restrict__ Cc)
{
    const long long z = blockIdx.z;
    A  += z * (long long)NP_ * IC_;
    Cc += z * (long long)N_ * C_;

    const int m0 = blockIdx.x * 64;
    const int n0 = blockIdx.y * 64;
    const int tid = threadIdx.x;
    const int w = tid >> 5, lane = tid & 31;
    const int gid = lane >> 2, tig = lane & 3;
    const int wm = (w & 1) * 32, wn = (w >> 1) * 32;

    __shared__ uint32_t As[64 * FSTR];
    __shared__ uint32_t Bs[64 * FSTR];
    __shared__ float csum[64];
    __shared__ float csq [64];

    if (tid < 64) { csum[tid] = 0.f; csq[tid] = 0.f; }

    const int a_row = (lane & 7) + ((lane >> 3) & 1) * 8;
    const int a_kb  = (lane >> 4) * 16;
    const int b_row = (lane & 7) + (lane >> 4) * 8;
    const int b_kb  = ((lane >> 3) & 1) * 16;

    float acc[2][4][4];
    #pragma unroll
    for (int i = 0; i < 2; i++)
        #pragma unroll
        for (int j = 0; j < 4; j++)
            #pragma unroll
            for (int r = 0; r < 4; r++) acc[i][j][r] = 0.0f;

    for (int k0 = 0; k0 < IC_; k0 += 32) {
        #pragma unroll
        for (int it = 0; it < 2; it++) {
            int lin = tid + it * 128;
            int row = lin >> 2, k8 = (lin & 3) << 3, kw = (lin & 3) << 2;
            *(uint4*)(&As[row * FSTR + kw]) =
                *(const uint4*)(A + (long long)(m0 + row) * IC_ + k0 + k8);
            *(uint4*)(&Bs[row * FSTR + kw]) =
                *(const uint4*)(g_wzh + (long long)(n0 + row) * IC_ + k0 + k8);
        }
        __syncthreads();

        const uint32_t abase = smem_u32(As);
        const uint32_t bbase = smem_u32(Bs);
        #pragma unroll
        for (int ks = 0; ks < 2; ks++) {
            const int kb = ks * 32;
            uint32_t af[2][4];
            #pragma unroll
            for (int i = 0; i < 2; i++)
                ldsm_x4(af[i][0], af[i][1], af[i][2], af[i][3],
                        abase + (wm + i * 16 + a_row) * FSTRB + kb + a_kb);
            uint32_t bf[4][2];
            #pragma unroll
            for (int jj = 0; jj < 2; jj++)
                ldsm_x4(bf[jj * 2][0], bf[jj * 2][1], bf[jj * 2 + 1][0], bf[jj * 2 + 1][1],
                        bbase + (wn + jj * 16 + b_row) * FSTRB + kb + b_kb);
            #pragma unroll
            for (int i = 0; i < 2; i++)
                #pragma unroll
                for (int j = 0; j < 4; j++)
                    mma_f16(acc[i][j][0], acc[i][j][1], acc[i][j][2], acc[i][j][3],
                            af[i][0], af[i][1], af[i][2], af[i][3],
                            bf[j][0], bf[j][1]);
        }
        __syncthreads();
    }

    #pragma unroll
    for (int j = 0; j < 4; j++) {
        int lcol = wn + j * 8 + tig * 2;
        int gcol = n0 + lcol;
        float b0v = bias[gcol], b1v = bias[gcol + 1];
        float s0 = 0.f, q0 = 0.f, s1 = 0.f, q1 = 0.f;
        #pragma unroll
        for (int i = 0; i < 2; i++) {
            int grow = m0 + wm + i * 16 + gid;
            float v00 = acc[i][j][0] + b0v;
            float v01 = acc[i][j][1] + b1v;
            float v10 = acc[i][j][2] + b0v;
            float v11 = acc[i][j][3] + b1v;
            *(float2*)(Cc + (long long)grow * C_ + gcol)       = make_float2(v00, v01);
            *(float2*)(Cc + (long long)(grow + 8) * C_ + gcol) = make_float2(v10, v11);
            s0 += v00 + v10;  q0 += v00 * v00 + v10 * v10;
            s1 += v01 + v11;  q1 += v01 * v01 + v11 * v11;
        }
        atomicAdd(&csum[lcol],     s0);
        atomicAdd(&csq [lcol],     q0);
        atomicAdd(&csum[lcol + 1], s1);
        atomicAdd(&csq [lcol + 1], q1);
    }
    __syncthreads();
    if (tid < 64) {
        atomicAdd(&g_sum  [n0 + tid], (double)csum[tid]);
        atomicAdd(&g_sumsq[n0 + tid], (double)csq [tid]);
    }
}

// ---------------------------------------------------------------------------
// BN: zero stats + final (unchanged)
// ---------------------------------------------------------------------------
__global__ void zero_stats()
{
    int t = threadIdx.x;
    g_sum[t] = 0.0;
    g_sumsq[t] = 0.0;
}

__global__ __launch_bounds__(256) void bn_final(
    const float* __restrict__ x,
    const float* __restrict__ bn_w, const float* __restrict__ bn_b,
    float* __restrict__ out)
{
    __shared__ float t[32][33];
    const int b  = blockIdx.z;
    const int c0 = blockIdx.y * 32;
    const int n0 = blockIdx.x * 32;
    const int tx = threadIdx.x, ty = threadIdx.y;

    #pragma unroll
    for (int j = 0; j < 32; j += 8) {
        int n = n0 + ty + j;
        t[ty + j][tx] = g_y2[((size_t)(b * N_ + n)) * C_ + c0 + tx];
    }
    __syncthreads();

    const double cnt = (double)ROWS_TOTAL;
    #pragma unroll
    for (int j = 0; j < 32; j += 8) {
        int c = c0 + ty + j;
        double mean = g_sum[c] / cnt;
        double var  = g_sumsq[c] / cnt - mean * mean;
        float inv = (float)rsqrt(var + 1e-5);
        float w = bn_w[c], bb = bn_b[c];
        int n = n0 + tx;
        size_t oidx = ((size_t)b * C_ + c) * (size_t)N_ + n;
        float v = t[tx][ty + j];
        out[oidx] = (v - (float)mean) * inv * w + bb + x[oidx];
    }
}

// ---------------------------------------------------------------------------
// Launch
// ---------------------------------------------------------------------------
extern "C" void kernel_launch(void* const* d_in, const int* in_sizes, int n_in,
                              void* d_out, int out_size)
{
    const float* x       = (const float*)d_in[0];
    const float* theta_w = (const float*)d_in[1];
    const float* theta_b = (const float*)d_in[2];
    const float* phi_w   = (const float*)d_in[3];
    const float* phi_b   = (const float*)d_in[4];
    const float* gw      = (const float*)d_in[5];
    const float* gb      = (const float*)d_in[6];
    const float* wz_w    = (const float*)d_in[7];
    const float* wz_b    = (const float*)d_in[8];
    const float* bn_w    = (const float*)d_in[9];
    const float* bn_b    = (const float*)d_in[10];
    float* out = (float*)d_out;

    float *y2;
    __half *Qh, *Kh, *Vt, *y1h;
    cudaGetSymbolAddress((void**)&Qh,  g_Qh);
    cudaGetSymbolAddress((void**)&Kh,  g_Kh);
    cudaGetSymbolAddress((void**)&Vt,  g_Vt);
    cudaGetSymbolAddress((void**)&y1h, g_y1h);
    cudaGetSymbolAddress((void**)&y2,  g_y2);

    cudaFuncSetAttribute(flash_attn,
                         cudaFuncAttributeMaxDynamicSharedMemorySize, SM_TOTAL);

    zero_stats<<<1, 512>>>();

    conv_weights<<<(4 * IC_ * C_) / 256, 256>>>(theta_w, phi_w, gw, wz_w);
    x_to_h<<<dim3(N_ / 32, C_ / 32, B_), dim3(32, 8)>>>(x);

    qkv3_f16<<<dim3(N_ / 64, IC_ / 64, B_), 256>>>(
        theta_b, phi_b, gb, Qh, Kh, Vt);

    // fused attention: S + softmax + PV
    flash_attn<<<dim3(NP_ / QT, B_), 256, SM_TOTAL>>>(Qh, Kh, Vt, y1h);

    y2h_stats<<<dim3(N_ / 64, C_ / 64, B_), 128>>>(y1h, wz_b, y2);

    bn_final<<<dim3(N_ / 32, C_ / 32, B_), dim3(32, 8)>>>(x, bn_w, bn_b, out);
}